// round 10
// baseline (speedup 1.0000x reference)
#include <cuda_runtime.h>
#include <cuda_bf16.h>
#include <math.h>
#include <stdint.h>

// Problem constants
#define BB   2048
#define CC   64
#define DH   512
#define K3   1536
#define NB2  (K3 + DH)                 // concat fold-B rows
#define SCALE 0.044194173824159216f   // 1/sqrt(512)

typedef unsigned long long u64;
typedef __nv_bfloat16 bf16;

// ---------------- scratch (static device globals) ----------------
__device__ bf16  g_ctx_h [BB * K3];
__device__ bf16  g_ctx_l [BB * K3];
__device__ bf16  g_WBT_h [NB2 * DH];  // rows 0..1535: WqT[i,e]; rows 1536..2047: WvT[e2,e]
__device__ bf16  g_WBT_l [NB2 * DH];
__device__ bf16  g_WkT_h [DH * DH];
__device__ bf16  g_WkT_l [DH * DH];
__device__ bf16  g_W1t_h [DH * K3];   // W1t[d,i] = sum_e WkT[d,e]*WqT[i,e]
__device__ bf16  g_W1t_l [DH * K3];
__device__ bf16  g_M2t_h [DH * DH];   // M2t[d,e2] = sum_e WkT[d,e]*WvT[e2,e]
__device__ bf16  g_M2t_l [DH * DH];
__device__ float g_qt    [BB * DH];
__device__ bf16  g_gbar_h[BB * DH];
__device__ bf16  g_gbar_l[BB * DH];
__device__ float g_kt    [BB * DH];
__device__ int   g_dbl_is_u8;

// ---------------- helpers ----------------
__device__ __forceinline__ uint32_t smem_u32(const void* p) {
    uint32_t a;
    asm("{ .reg .u64 t; cvta.to.shared.u64 t, %1; cvt.u32.u64 %0, t; }" : "=r"(a) : "l"(p));
    return a;
}
__device__ __forceinline__ void cp_async16(uint32_t dst, const void* src) {
    asm volatile("cp.async.cg.shared.global [%0], [%1], 16;" :: "r"(dst), "l"(src) : "memory");
}
__device__ __forceinline__ void cp_commit() {
    asm volatile("cp.async.commit_group;" ::: "memory");
}
__device__ __forceinline__ void split_bf16(float f, bf16& h, bf16& l) {
    h = __float2bfloat16_rn(f);
    l = __float2bfloat16_rn(f - __bfloat162float(h));
}
__device__ __forceinline__ void mma_bf16(float* c, const uint32_t* a, const uint32_t* b) {
    asm volatile(
        "mma.sync.aligned.m16n8k16.row.col.f32.bf16.bf16.f32 "
        "{%0,%1,%2,%3}, {%4,%5,%6,%7}, {%8,%9}, {%0,%1,%2,%3};"
        : "+f"(c[0]), "+f"(c[1]), "+f"(c[2]), "+f"(c[3])
        : "r"(a[0]), "r"(a[1]), "r"(a[2]), "r"(a[3]), "r"(b[0]), "r"(b[1]));
}
__device__ __forceinline__ void ldmx4(uint32_t* r, uint32_t saddr) {
    asm volatile("ldmatrix.sync.aligned.m8n8.x4.shared.b16 {%0,%1,%2,%3}, [%4];"
        : "=r"(r[0]), "=r"(r[1]), "=r"(r[2]), "=r"(r[3]) : "r"(saddr));
}

// ---------------- prep: transposes+splits, context pack, dtype sniff ----------------
__global__ void prep_kernel(const float* __restrict__ Wq,
                            const float* __restrict__ Wk,
                            const float* __restrict__ Wv,
                            bf16* __restrict__ wbh, bf16* __restrict__ wbl,
                            bf16* __restrict__ wkh, bf16* __restrict__ wkl,
                            uint2* __restrict__ ch, uint2* __restrict__ cl,
                            const float4* __restrict__ hx,
                            const float4* __restrict__ hs,
                            const float4* __restrict__ eq,
                            const unsigned char* __restrict__ dblp) {
    int bid = blockIdx.x;
    if (bid == 1280) {
        __shared__ int any;
        if (threadIdx.x == 0) any = 0;
        __syncthreads();
        int found = 0;
        for (int i = threadIdx.x; i < 2048; i += 256)
            if ((i & 3) && dblp[i]) found = 1;
        if (found) any = 1;
        __syncthreads();
        if (threadIdx.x == 0) g_dbl_is_u8 = any;
        return;
    }
    if (bid > 1280) {
        int idx = (bid - 1281) * 256 + threadIdx.x;   // BB*384 float4s
        int b = idx / 384;
        int r = idx - b * 384;
        float4 v;
        if (r < 128)       v = hx[b * 128 + r];
        else if (r < 256)  v = hs[b * 128 + (r - 128)];
        else               v = eq[b * 128 + (r - 256)];
        bf16 h0,l0,h1,l1,h2,l2,h3,l3;
        split_bf16(v.x,h0,l0); split_bf16(v.y,h1,l1);
        split_bf16(v.z,h2,l2); split_bf16(v.w,h3,l3);
        __nv_bfloat162 H01 = {h0,h1}, H23 = {h2,h3}, L01 = {l0,l1}, L23 = {l2,l3};
        ch[idx] = make_uint2(*(uint32_t*)&H01, *(uint32_t*)&H23);
        cl[idx] = make_uint2(*(uint32_t*)&L01, *(uint32_t*)&L23);
        return;
    }
    int tx = threadIdx.x & 31, ty = threadIdx.x >> 5;   // 32 x 8
    const float* in; bf16 *oh, *ol; int Cn, bx, by, roff;
    if (bid < 768)       { in = Wq; oh = wbh; ol = wbl; Cn = K3; bx = bid % 48;          by = bid / 48;         roff = 0; }
    else if (bid < 1024) { in = Wk; oh = wkh; ol = wkl; Cn = DH; bx = (bid - 768) & 15;  by = (bid - 768) >> 4; roff = 0; }
    else                 { in = Wv; oh = wbh; ol = wbl; Cn = DH; bx = (bid - 1024) & 15; by = (bid - 1024) >> 4; roff = K3; }
    __shared__ float t[32][33];
    int i0 = bx * 32, e0 = by * 32;
    #pragma unroll
    for (int j = 0; j < 32; j += 8)
        t[ty + j][tx] = in[(size_t)(e0 + ty + j) * Cn + i0 + tx];
    __syncthreads();
    #pragma unroll
    for (int j = 0; j < 32; j += 8) {
        float f = t[tx][ty + j];
        bf16 h, l; split_bf16(f, h, l);
        size_t o = (size_t)(roff + i0 + ty + j) * DH + e0 + tx;
        oh[o] = h; ol[o] = l;
    }
}

// ---------------- mma.sync GEMM (R7 config) ----------------
#define MG_AH   0
#define MG_AL   5120
#define MG_BH   10240
#define MG_BL   15360
#define MG_STG  20480
#define MG_SMEM (3 * MG_STG)

template<int MODE>
__global__ void __launch_bounds__(128, 2) mma_gemm_kernel(
    float* __restrict__ outf,
    bf16* __restrict__ o1h, bf16* __restrict__ o1l,
    bf16* __restrict__ o2h, bf16* __restrict__ o2l,
    const bf16* __restrict__ Ah, const bf16* __restrict__ Al,
    const bf16* __restrict__ Bh, const bf16* __restrict__ Bl,
    int N, int K)
{
    extern __shared__ char dsm[];
    uint32_t sb0 = smem_u32(dsm);

    int tid = threadIdx.x;
    int lane = tid & 31, wid = tid >> 5;
    int wm = wid & 1, wn = wid >> 1;
    int gid = lane >> 2, tid4 = lane & 3;
    int lr = lane & 7, sel = lane >> 3;
    int bm = blockIdx.y * 64, bn = blockIdx.x * 64;
    int KB = K >> 5;

    uint32_t a_row    = (uint32_t)(wm * 32 + lr + (sel & 1) * 8);
    uint32_t a_coloff = (uint32_t)((sel >> 1) * 8);
    uint32_t b_row    = (uint32_t)(wn * 32 + lr + (sel >> 1) * 8);
    uint32_t b_coloff = (uint32_t)((sel & 1) * 8);

    float C[2][4][4];
    #pragma unroll
    for (int t = 0; t < 2; t++)
        #pragma unroll
        for (int j = 0; j < 4; j++)
            #pragma unroll
            for (int q = 0; q < 4; q++) C[t][j][q] = 0.f;

    auto load_stage = [&](int kb, int s) {
        uint32_t sb = sb0 + s * MG_STG;
        int ko = kb * 32;
        #pragma unroll
        for (int i = 0; i < 8; i++) {
            int v = tid + i * 128;
            if (v < 256) {
                int r = v >> 2, c = v & 3;
                cp_async16(sb + MG_AH + r * 80 + c * 16,
                           Ah + (size_t)(bm + r) * K + ko + c * 8);
            } else if (v < 512) {
                int u = v - 256; int r = u >> 2, c = u & 3;
                cp_async16(sb + MG_AL + r * 80 + c * 16,
                           Al + (size_t)(bm + r) * K + ko + c * 8);
            } else if (v < 768) {
                int u = v - 512; int r = u >> 2, c = u & 3;
                cp_async16(sb + MG_BH + r * 80 + c * 16,
                           Bh + (size_t)(bn + r) * K + ko + c * 8);
            } else {
                int u = v - 768; int r = u >> 2, c = u & 3;
                cp_async16(sb + MG_BL + r * 80 + c * 16,
                           Bl + (size_t)(bn + r) * K + ko + c * 8);
            }
        }
        cp_commit();
    };

    load_stage(0, 0);
    if (KB > 1) load_stage(1, 1);

    for (int kb = 0; kb < KB; kb++) {
        if (kb + 2 < KB) {
            load_stage(kb + 2, (kb + 2) % 3);
            asm volatile("cp.async.wait_group 2;" ::: "memory");
        } else if (kb + 1 < KB) {
            asm volatile("cp.async.wait_group 1;" ::: "memory");
        } else {
            asm volatile("cp.async.wait_group 0;" ::: "memory");
        }
        __syncthreads();

        uint32_t st = sb0 + (kb % 3) * MG_STG;
        #pragma unroll
        for (int step = 0; step < 2; step++) {
            int kbase = step * 16;
            uint32_t ah[2][4], al[2][4], bh[8], bl[8];
            #pragma unroll
            for (int t = 0; t < 2; t++) {
                uint32_t aa = st + MG_AH + (a_row + t * 16) * 80 + (kbase + a_coloff) * 2;
                ldmx4(ah[t], aa);
                ldmx4(al[t], aa + (MG_AL - MG_AH));
            }
            #pragma unroll
            for (int jp = 0; jp < 2; jp++) {
                uint32_t ba = st + MG_BH + (b_row + jp * 16) * 80 + (kbase + b_coloff) * 2;
                ldmx4(&bh[jp * 4], ba);
                ldmx4(&bl[jp * 4], ba + (MG_BL - MG_BH));
            }
            #pragma unroll
            for (int t = 0; t < 2; t++)
                #pragma unroll
                for (int j = 0; j < 4; j++) {
                    mma_bf16(C[t][j], ah[t], &bh[j * 2]);
                    mma_bf16(C[t][j], ah[t], &bl[j * 2]);
                    mma_bf16(C[t][j], al[t], &bh[j * 2]);
                }
        }
        __syncthreads();
    }

    bf16 *ph = o1h, *pl = o1l;
    int nstride = K3, coff = 0;
    if (MODE == 2 && bn >= K3) { ph = o2h; pl = o2l; nstride = DH; coff = K3; }
    #pragma unroll
    for (int t = 0; t < 2; t++) {
        int m0 = bm + wm * 32 + t * 16 + gid;
        #pragma unroll
        for (int j = 0; j < 4; j++) {
            int col = bn + wn * 32 + j * 8 + tid4 * 2;
            if (MODE == 2) {
                bf16 h0,l0,h1,l1;
                split_bf16(C[t][j][0], h0, l0); split_bf16(C[t][j][1], h1, l1);
                __nv_bfloat162 H = {h0,h1}, L = {l0,l1};
                *(uint32_t*)(ph + (size_t)m0 * nstride + col - coff) = *(uint32_t*)&H;
                *(uint32_t*)(pl + (size_t)m0 * nstride + col - coff) = *(uint32_t*)&L;
                split_bf16(C[t][j][2], h0, l0); split_bf16(C[t][j][3], h1, l1);
                __nv_bfloat162 H2 = {h0,h1}, L2 = {l0,l1};
                *(uint32_t*)(ph + (size_t)(m0 + 8) * nstride + col - coff) = *(uint32_t*)&H2;
                *(uint32_t*)(pl + (size_t)(m0 + 8) * nstride + col - coff) = *(uint32_t*)&L2;
            } else {
                *(float2*)(outf + (size_t)m0 * N + col)       = make_float2(C[t][j][0], C[t][j][1]);
                *(float2*)(outf + (size_t)(m0 + 8) * N + col) = make_float2(C[t][j][2], C[t][j][3]);
            }
        }
    }
}

// ---------------- fused pass 1: zero-tile (L2 re-read) + factored embeddings ----------------
// logit_c = (h_c.q + cq[cap_c] + dq[dist_c]) * SCALE
// gbar_d  = sum_c attn_c HtC[c,d] (L2 re-read)
//         + sum_v wcap[v] cemb[v,d] + sum_u wdist[u] demb[u,d]
__global__ void __launch_bounds__(512) fused1_kernel(
    const float* __restrict__ HtC, const int* __restrict__ caps,
    const int* __restrict__ dists, const float* __restrict__ cemb,
    const float* __restrict__ demb, const float* __restrict__ qt,
    bf16* __restrict__ gbh, bf16* __restrict__ gbl)
{
    int b = blockIdx.x, tid = threadIdx.x;
    int w = tid >> 5, l = tid & 31;
    __shared__ __align__(16) float qs[DH];
    __shared__ int   cap_s[CC], dist_s[CC];
    __shared__ float cq_s[11], dq_s[3], wcap_s[11], wdist_s[3];
    __shared__ float logit_s[CC], attn_s[CC];

    qs[tid] = qt[(size_t)b * DH + tid];
    if (tid < CC) {
        cap_s[tid]  = caps[b * CC + tid];
        dist_s[tid] = dists[b * CC + tid];
    }
    __syncthreads();

    // table dots: warps 0..10 -> cq, 11..13 -> dq (raw; scaling later)
    if (w < 14) {
        const float* trow = (w < 11) ? cemb + w * DH : demb + (w - 11) * DH;
        float a = 0.f;
        #pragma unroll
        for (int i = l; i < DH; i += 32) a += trow[i] * qs[i];
        #pragma unroll
        for (int o = 16; o; o >>= 1) a += __shfl_xor_sync(0xffffffffu, a, o);
        if (l == 0) { if (w < 11) cq_s[w] = a; else dq_s[w - 11] = a; }
    }

    // raw row dots (default .ca loads: tile stays resident in L2 for gbar re-read)
    const float4* H4 = (const float4*)HtC + (size_t)b * (CC * DH / 4);
    const float4* q4 = (const float4*)qs;
    #pragma unroll
    for (int r = 0; r < 4; r++) {
        int c = w * 4 + r;
        const float4* hrow = H4 + c * 128;
        float acc = 0.f;
        #pragma unroll
        for (int j = 0; j < 4; j++) {
            int i = j * 32 + l;
            float4 h = hrow[i];
            acc += h.x * q4[i].x + h.y * q4[i].y + h.z * q4[i].z + h.w * q4[i].w;
        }
        #pragma unroll
        for (int o = 16; o; o >>= 1) acc += __shfl_xor_sync(0xffffffffu, acc, o);
        if (l == 0) logit_s[c] = acc;
    }
    __syncthreads();

    if (w == 0) {
        float x0 = (logit_s[l]      + cq_s[cap_s[l]]      + dq_s[dist_s[l]])      * SCALE;
        float x1 = (logit_s[l + 32] + cq_s[cap_s[l + 32]] + dq_s[dist_s[l + 32]]) * SCALE;
        float m = fmaxf(x0, x1);
        #pragma unroll
        for (int o = 16; o; o >>= 1) m = fmaxf(m, __shfl_xor_sync(0xffffffffu, m, o));
        float e0 = expf(x0 - m), e1 = expf(x1 - m);
        float s = e0 + e1;
        #pragma unroll
        for (int o = 16; o; o >>= 1) s += __shfl_xor_sync(0xffffffffu, s, o);
        float inv = 1.f / s;
        attn_s[l] = e0 * inv; attn_s[l + 32] = e1 * inv;
    }
    __syncthreads();

    // index-grouped attn weights
    if (tid < 11) {
        float s = 0.f;
        for (int c = 0; c < CC; c++) if (cap_s[c] == tid) s += attn_s[c];
        wcap_s[tid] = s;
    }
    if (tid >= 32 && tid < 35) {
        int u = tid - 32; float s = 0.f;
        for (int c = 0; c < CC; c++) if (dist_s[c] == u) s += attn_s[c];
        wdist_s[u] = s;
    }
    __syncthreads();

    // gbar over d = tid: all rows from L2, plus tables
    const float* Hb = HtC + (size_t)b * (CC * DH);
    float acc = 0.f;
    #pragma unroll 8
    for (int c = 0; c < CC; c++)
        acc = fmaf(attn_s[c], Hb[c * DH + tid], acc);
    #pragma unroll
    for (int v = 0; v < 11; v++)
        acc = fmaf(wcap_s[v], cemb[v * DH + tid], acc);
    #pragma unroll
    for (int u = 0; u < 3; u++)
        acc = fmaf(wdist_s[u], demb[u * DH + tid], acc);
    bf16 h, lo; split_bf16(acc, h, lo);
    gbh[(size_t)b * DH + tid] = h;
    gbl[(size_t)b * DH + tid] = lo;
}

// ---------------- fused pass 2: pure streaming dots + factored embeddings ----------------
__global__ void __launch_bounds__(512) fused2_kernel(
    const float* __restrict__ HtC, const int* __restrict__ caps,
    const int* __restrict__ dists, const float* __restrict__ cemb,
    const float* __restrict__ demb, const float* __restrict__ kt,
    const void* __restrict__ dbl, float* __restrict__ out)
{
    int b = blockIdx.x, tid = threadIdx.x;
    int w = tid >> 5, l = tid & 31;
    __shared__ __align__(16) float ks[DH];
    __shared__ int   cap_s[CC], dist_s[CC];
    __shared__ float ck_s[11], dk_s[3];
    __shared__ float u_s[CC];

    ks[tid] = kt[(size_t)b * DH + tid];
    if (tid < CC) {
        cap_s[tid]  = caps[b * CC + tid];
        dist_s[tid] = dists[b * CC + tid];
    }
    __syncthreads();

    if (w < 14) {
        const float* trow = (w < 11) ? cemb + w * DH : demb + (w - 11) * DH;
        float a = 0.f;
        #pragma unroll
        for (int i = l; i < DH; i += 32) a += trow[i] * ks[i];
        #pragma unroll
        for (int o = 16; o; o >>= 1) a += __shfl_xor_sync(0xffffffffu, a, o);
        if (l == 0) { if (w < 11) ck_s[w] = a; else dk_s[w - 11] = a; }
    }

    const float4* H4 = (const float4*)HtC + (size_t)b * (CC * DH / 4);
    const float4* k4 = (const float4*)ks;
    #pragma unroll
    for (int r = 0; r < 4; r++) {
        int c = w * 4 + r;
        const float4* hrow = H4 + c * 128;
        float acc = 0.f;
        #pragma unroll
        for (int j = 0; j < 4; j++) {
            int i = j * 32 + l;
            float4 h = __ldcs(hrow + i);
            acc += h.x * k4[i].x + h.y * k4[i].y + h.z * k4[i].z + h.w * k4[i].w;
        }
        #pragma unroll
        for (int o = 16; o; o >>= 1) acc += __shfl_xor_sync(0xffffffffu, acc, o);
        if (l == 0) u_s[c] = acc;
    }
    __syncthreads();

    if (w == 0) {
        int dval = g_dbl_is_u8 ? (int)((const unsigned char*)dbl)[b]
                               : ((const int*)dbl)[b];
        int need = dval ? 2 : 1;
        float x0 = (u_s[l]      + ck_s[cap_s[l]]      + dk_s[dist_s[l]])      * SCALE;
        float x1 = (u_s[l + 32] + ck_s[cap_s[l + 32]] + dk_s[dist_s[l + 32]]) * SCALE;
        if (cap_s[l]      < need) x0 = __int_as_float(0xff800000);
        if (cap_s[l + 32] < need) x1 = __int_as_float(0xff800000);
        float m = fmaxf(x0, x1);
        #pragma unroll
        for (int o = 16; o; o >>= 1) m = fmaxf(m, __shfl_xor_sync(0xffffffffu, m, o));
        float e0 = expf(x0 - m), e1 = expf(x1 - m);
        float s = e0 + e1;
        #pragma unroll
        for (int o = 16; o; o >>= 1) s += __shfl_xor_sync(0xffffffffu, s, o);
        float inv = 1.f / s;
        out[(size_t)b * CC + l]      = e0 * inv;
        out[(size_t)b * CC + l + 32] = e1 * inv;
    }
}

extern "C" void kernel_launch(void* const* d_in, const int* in_sizes, int n_in,
                              void* d_out, int out_size) {
    const float* HtC   = (const float*)d_in[0];
    const int*   caps  = (const int*)  d_in[1];
    const int*   dists = (const int*)  d_in[2];
    const float* HX    = (const float*)d_in[3];
    const float* HS    = (const float*)d_in[4];
    const float* EQ    = (const float*)d_in[5];
    const void*  dbl   = d_in[6];
    const float* cemb  = (const float*)d_in[7];
    const float* demb  = (const float*)d_in[8];
    const float* Wq    = (const float*)d_in[9];
    const float* Wk    = (const float*)d_in[10];
    const float* Wv    = (const float*)d_in[11];
    float* out = (float*)d_out;

    bf16 *ctxh,*ctxl,*wbh,*wbl,*wkh,*wkl,*w1h,*w1l,*m2h,*m2l,*gbh,*gbl;
    float *qt,*kt;
    cudaGetSymbolAddress((void**)&ctxh, g_ctx_h);  cudaGetSymbolAddress((void**)&ctxl, g_ctx_l);
    cudaGetSymbolAddress((void**)&wbh,  g_WBT_h);  cudaGetSymbolAddress((void**)&wbl,  g_WBT_l);
    cudaGetSymbolAddress((void**)&wkh,  g_WkT_h);  cudaGetSymbolAddress((void**)&wkl,  g_WkT_l);
    cudaGetSymbolAddress((void**)&w1h,  g_W1t_h);  cudaGetSymbolAddress((void**)&w1l,  g_W1t_l);
    cudaGetSymbolAddress((void**)&m2h,  g_M2t_h);  cudaGetSymbolAddress((void**)&m2l,  g_M2t_l);
    cudaGetSymbolAddress((void**)&gbh,  g_gbar_h); cudaGetSymbolAddress((void**)&gbl,  g_gbar_l);
    cudaGetSymbolAddress((void**)&qt,   g_qt);     cudaGetSymbolAddress((void**)&kt,   g_kt);

    cudaFuncSetAttribute(mma_gemm_kernel<0>, cudaFuncAttributeMaxDynamicSharedMemorySize, MG_SMEM);
    cudaFuncSetAttribute(mma_gemm_kernel<2>, cudaFuncAttributeMaxDynamicSharedMemorySize, MG_SMEM);

    // 1) prep: weight transposes (B concat) + context pack/split + dtype sniff
    prep_kernel<<<4353, 256>>>(Wq, Wk, Wv, wbh, wbl, wkh, wkl,
                               (uint2*)ctxh, (uint2*)ctxl,
                               (const float4*)HX, (const float4*)HS, (const float4*)EQ,
                               (const unsigned char*)dbl);
    // 2) fold (merged): D[d, 0..2047] = sum_e WkT[d,e]*WBT[n,e] -> W1t | M2t
    mma_gemm_kernel<2><<<dim3(NB2/64, DH/64), 128, MG_SMEM>>>(
        nullptr, w1h, w1l, m2h, m2l, wkh, wkl, wbh, wbl, NB2, DH);
    // 3) qt[b,d] = sum_i ctx[b,i]*W1t[d,i]    (M=2048, N=512, K=1536)
    mma_gemm_kernel<0><<<dim3(DH/64, BB/64), 128, MG_SMEM>>>(
        qt, nullptr, nullptr, nullptr, nullptr, ctxh, ctxl, w1h, w1l, DH, K3);
    // 4) logits/softmax/gbar (no tile; L2 re-read; 4 CTAs/SM)
    fused1_kernel<<<BB, 512>>>(HtC, caps, dists, cemb, demb, qt, gbh, gbl);
    // 5) kt[b,d] = sum_e2 gbar[b,e2]*M2t[d,e2] (M=2048, N=512, K=512)
    mma_gemm_kernel<0><<<dim3(DH/64, BB/64), 128, MG_SMEM>>>(
        kt, nullptr, nullptr, nullptr, nullptr, gbh, gbl, m2h, m2l, DH, DH);
    // 6) u/mask/softmax -> out (streaming, factored embeddings)
    fused2_kernel<<<BB, 512>>>(HtC, caps, dists, cemb, demb, kt, dbl, out);
}

// round 11
// speedup vs baseline: 1.0354x; 1.0354x over previous
#include <cuda_runtime.h>
#include <cuda_bf16.h>
#include <math.h>
#include <stdint.h>

// Problem constants
#define BB   2048
#define CC   64
#define DH   512
#define K3   1536
#define NB2  (K3 + DH)                 // concat fold-B rows
#define SCALE 0.044194173824159216f   // 1/sqrt(512)

typedef unsigned long long u64;
typedef __nv_bfloat16 bf16;

// ---------------- scratch (static device globals) ----------------
__device__ bf16  g_ctx_h [BB * K3];
__device__ bf16  g_ctx_l [BB * K3];
__device__ bf16  g_WBT_h [NB2 * DH];  // rows 0..1535: WqT[i,e]; rows 1536..2047: WvT[e2,e]
__device__ bf16  g_WBT_l [NB2 * DH];
__device__ bf16  g_WkT_h [DH * DH];
__device__ bf16  g_WkT_l [DH * DH];
__device__ bf16  g_W1t_h [DH * K3];   // W1t[d,i] = sum_e WkT[d,e]*WqT[i,e]
__device__ bf16  g_W1t_l [DH * K3];
__device__ bf16  g_M2t_h [DH * DH];   // M2t[d,e2] = sum_e WkT[d,e]*WvT[e2,e]
__device__ bf16  g_M2t_l [DH * DH];
__device__ float g_qt    [BB * DH];
__device__ bf16  g_gbar_h[BB * DH];
__device__ bf16  g_gbar_l[BB * DH];
__device__ float g_kt    [BB * DH];
__device__ int   g_dbl_is_u8;

// ---------------- helpers ----------------
__device__ __forceinline__ uint32_t smem_u32(const void* p) {
    uint32_t a;
    asm("{ .reg .u64 t; cvta.to.shared.u64 t, %1; cvt.u32.u64 %0, t; }" : "=r"(a) : "l"(p));
    return a;
}
__device__ __forceinline__ void cp_async16(uint32_t dst, const void* src) {
    asm volatile("cp.async.cg.shared.global [%0], [%1], 16;" :: "r"(dst), "l"(src) : "memory");
}
__device__ __forceinline__ void cp_commit() {
    asm volatile("cp.async.commit_group;" ::: "memory");
}
__device__ __forceinline__ void split_bf16(float f, bf16& h, bf16& l) {
    h = __float2bfloat16_rn(f);
    l = __float2bfloat16_rn(f - __bfloat162float(h));
}
__device__ __forceinline__ void mma_bf16(float* c, const uint32_t* a, const uint32_t* b) {
    asm volatile(
        "mma.sync.aligned.m16n8k16.row.col.f32.bf16.bf16.f32 "
        "{%0,%1,%2,%3}, {%4,%5,%6,%7}, {%8,%9}, {%0,%1,%2,%3};"
        : "+f"(c[0]), "+f"(c[1]), "+f"(c[2]), "+f"(c[3])
        : "r"(a[0]), "r"(a[1]), "r"(a[2]), "r"(a[3]), "r"(b[0]), "r"(b[1]));
}
__device__ __forceinline__ void ldmx4(uint32_t* r, uint32_t saddr) {
    asm volatile("ldmatrix.sync.aligned.m8n8.x4.shared.b16 {%0,%1,%2,%3}, [%4];"
        : "=r"(r[0]), "=r"(r[1]), "=r"(r[2]), "=r"(r[3]) : "r"(saddr));
}

// ---------------- prep: transposes+splits, context pack, dtype sniff ----------------
__global__ void prep_kernel(const float* __restrict__ Wq,
                            const float* __restrict__ Wk,
                            const float* __restrict__ Wv,
                            bf16* __restrict__ wbh, bf16* __restrict__ wbl,
                            bf16* __restrict__ wkh, bf16* __restrict__ wkl,
                            uint2* __restrict__ ch, uint2* __restrict__ cl,
                            const float4* __restrict__ hx,
                            const float4* __restrict__ hs,
                            const float4* __restrict__ eq,
                            const unsigned char* __restrict__ dblp) {
    int bid = blockIdx.x;
    if (bid == 1280) {
        __shared__ int any;
        if (threadIdx.x == 0) any = 0;
        __syncthreads();
        int found = 0;
        for (int i = threadIdx.x; i < 2048; i += 256)
            if ((i & 3) && dblp[i]) found = 1;
        if (found) any = 1;
        __syncthreads();
        if (threadIdx.x == 0) g_dbl_is_u8 = any;
        return;
    }
    if (bid > 1280) {
        int idx = (bid - 1281) * 256 + threadIdx.x;   // BB*384 float4s
        int b = idx / 384;
        int r = idx - b * 384;
        float4 v;
        if (r < 128)       v = hx[b * 128 + r];
        else if (r < 256)  v = hs[b * 128 + (r - 128)];
        else               v = eq[b * 128 + (r - 256)];
        bf16 h0,l0,h1,l1,h2,l2,h3,l3;
        split_bf16(v.x,h0,l0); split_bf16(v.y,h1,l1);
        split_bf16(v.z,h2,l2); split_bf16(v.w,h3,l3);
        __nv_bfloat162 H01 = {h0,h1}, H23 = {h2,h3}, L01 = {l0,l1}, L23 = {l2,l3};
        ch[idx] = make_uint2(*(uint32_t*)&H01, *(uint32_t*)&H23);
        cl[idx] = make_uint2(*(uint32_t*)&L01, *(uint32_t*)&L23);
        return;
    }
    int tx = threadIdx.x & 31, ty = threadIdx.x >> 5;   // 32 x 8
    const float* in; bf16 *oh, *ol; int Cn, bx, by, roff;
    if (bid < 768)       { in = Wq; oh = wbh; ol = wbl; Cn = K3; bx = bid % 48;          by = bid / 48;         roff = 0; }
    else if (bid < 1024) { in = Wk; oh = wkh; ol = wkl; Cn = DH; bx = (bid - 768) & 15;  by = (bid - 768) >> 4; roff = 0; }
    else                 { in = Wv; oh = wbh; ol = wbl; Cn = DH; bx = (bid - 1024) & 15; by = (bid - 1024) >> 4; roff = K3; }
    __shared__ float t[32][33];
    int i0 = bx * 32, e0 = by * 32;
    #pragma unroll
    for (int j = 0; j < 32; j += 8)
        t[ty + j][tx] = in[(size_t)(e0 + ty + j) * Cn + i0 + tx];
    __syncthreads();
    #pragma unroll
    for (int j = 0; j < 32; j += 8) {
        float f = t[tx][ty + j];
        bf16 h, l; split_bf16(f, h, l);
        size_t o = (size_t)(roff + i0 + ty + j) * DH + e0 + tx;
        oh[o] = h; ol[o] = l;
    }
}

// ---------------- mma.sync GEMM (R7 config) ----------------
#define MG_AH   0
#define MG_AL   5120
#define MG_BH   10240
#define MG_BL   15360
#define MG_STG  20480
#define MG_SMEM (3 * MG_STG)

template<int MODE>
__global__ void __launch_bounds__(128, 2) mma_gemm_kernel(
    float* __restrict__ outf,
    bf16* __restrict__ o1h, bf16* __restrict__ o1l,
    bf16* __restrict__ o2h, bf16* __restrict__ o2l,
    const bf16* __restrict__ Ah, const bf16* __restrict__ Al,
    const bf16* __restrict__ Bh, const bf16* __restrict__ Bl,
    int N, int K)
{
    extern __shared__ char dsm[];
    uint32_t sb0 = smem_u32(dsm);

    int tid = threadIdx.x;
    int lane = tid & 31, wid = tid >> 5;
    int wm = wid & 1, wn = wid >> 1;
    int gid = lane >> 2, tid4 = lane & 3;
    int lr = lane & 7, sel = lane >> 3;
    int bm = blockIdx.y * 64, bn = blockIdx.x * 64;
    int KB = K >> 5;

    uint32_t a_row    = (uint32_t)(wm * 32 + lr + (sel & 1) * 8);
    uint32_t a_coloff = (uint32_t)((sel >> 1) * 8);
    uint32_t b_row    = (uint32_t)(wn * 32 + lr + (sel >> 1) * 8);
    uint32_t b_coloff = (uint32_t)((sel & 1) * 8);

    float C[2][4][4];
    #pragma unroll
    for (int t = 0; t < 2; t++)
        #pragma unroll
        for (int j = 0; j < 4; j++)
            #pragma unroll
            for (int q = 0; q < 4; q++) C[t][j][q] = 0.f;

    auto load_stage = [&](int kb, int s) {
        uint32_t sb = sb0 + s * MG_STG;
        int ko = kb * 32;
        #pragma unroll
        for (int i = 0; i < 8; i++) {
            int v = tid + i * 128;
            if (v < 256) {
                int r = v >> 2, c = v & 3;
                cp_async16(sb + MG_AH + r * 80 + c * 16,
                           Ah + (size_t)(bm + r) * K + ko + c * 8);
            } else if (v < 512) {
                int u = v - 256; int r = u >> 2, c = u & 3;
                cp_async16(sb + MG_AL + r * 80 + c * 16,
                           Al + (size_t)(bm + r) * K + ko + c * 8);
            } else if (v < 768) {
                int u = v - 512; int r = u >> 2, c = u & 3;
                cp_async16(sb + MG_BH + r * 80 + c * 16,
                           Bh + (size_t)(bn + r) * K + ko + c * 8);
            } else {
                int u = v - 768; int r = u >> 2, c = u & 3;
                cp_async16(sb + MG_BL + r * 80 + c * 16,
                           Bl + (size_t)(bn + r) * K + ko + c * 8);
            }
        }
        cp_commit();
    };

    load_stage(0, 0);
    if (KB > 1) load_stage(1, 1);

    for (int kb = 0; kb < KB; kb++) {
        if (kb + 2 < KB) {
            load_stage(kb + 2, (kb + 2) % 3);
            asm volatile("cp.async.wait_group 2;" ::: "memory");
        } else if (kb + 1 < KB) {
            asm volatile("cp.async.wait_group 1;" ::: "memory");
        } else {
            asm volatile("cp.async.wait_group 0;" ::: "memory");
        }
        __syncthreads();

        uint32_t st = sb0 + (kb % 3) * MG_STG;
        #pragma unroll
        for (int step = 0; step < 2; step++) {
            int kbase = step * 16;
            uint32_t ah[2][4], al[2][4], bh[8], bl[8];
            #pragma unroll
            for (int t = 0; t < 2; t++) {
                uint32_t aa = st + MG_AH + (a_row + t * 16) * 80 + (kbase + a_coloff) * 2;
                ldmx4(ah[t], aa);
                ldmx4(al[t], aa + (MG_AL - MG_AH));
            }
            #pragma unroll
            for (int jp = 0; jp < 2; jp++) {
                uint32_t ba = st + MG_BH + (b_row + jp * 16) * 80 + (kbase + b_coloff) * 2;
                ldmx4(&bh[jp * 4], ba);
                ldmx4(&bl[jp * 4], ba + (MG_BL - MG_BH));
            }
            #pragma unroll
            for (int t = 0; t < 2; t++)
                #pragma unroll
                for (int j = 0; j < 4; j++) {
                    mma_bf16(C[t][j], ah[t], &bh[j * 2]);
                    mma_bf16(C[t][j], ah[t], &bl[j * 2]);
                    mma_bf16(C[t][j], al[t], &bh[j * 2]);
                }
        }
        __syncthreads();
    }

    bf16 *ph = o1h, *pl = o1l;
    int nstride = K3, coff = 0;
    if (MODE == 2 && bn >= K3) { ph = o2h; pl = o2l; nstride = DH; coff = K3; }
    #pragma unroll
    for (int t = 0; t < 2; t++) {
        int m0 = bm + wm * 32 + t * 16 + gid;
        #pragma unroll
        for (int j = 0; j < 4; j++) {
            int col = bn + wn * 32 + j * 8 + tid4 * 2;
            if (MODE == 2) {
                bf16 h0,l0,h1,l1;
                split_bf16(C[t][j][0], h0, l0); split_bf16(C[t][j][1], h1, l1);
                __nv_bfloat162 H = {h0,h1}, L = {l0,l1};
                *(uint32_t*)(ph + (size_t)m0 * nstride + col - coff) = *(uint32_t*)&H;
                *(uint32_t*)(pl + (size_t)m0 * nstride + col - coff) = *(uint32_t*)&L;
                split_bf16(C[t][j][2], h0, l0); split_bf16(C[t][j][3], h1, l1);
                __nv_bfloat162 H2 = {h0,h1}, L2 = {l0,l1};
                *(uint32_t*)(ph + (size_t)(m0 + 8) * nstride + col - coff) = *(uint32_t*)&H2;
                *(uint32_t*)(pl + (size_t)(m0 + 8) * nstride + col - coff) = *(uint32_t*)&L2;
            } else {
                *(float2*)(outf + (size_t)m0 * N + col)       = make_float2(C[t][j][0], C[t][j][1]);
                *(float2*)(outf + (size_t)(m0 + 8) * N + col) = make_float2(C[t][j][2], C[t][j][3]);
            }
        }
    }
}

// ---------------- fused pass 1: zero-tile (L2 re-read) + factored embeddings ----------------
// __launch_bounds__(512, 4): cap regs at 32 -> 4 CTAs/SM (100% warp occupancy)
__global__ void __launch_bounds__(512, 4) fused1_kernel(
    const float* __restrict__ HtC, const int* __restrict__ caps,
    const int* __restrict__ dists, const float* __restrict__ cemb,
    const float* __restrict__ demb, const float* __restrict__ qt,
    bf16* __restrict__ gbh, bf16* __restrict__ gbl)
{
    int b = blockIdx.x, tid = threadIdx.x;
    int w = tid >> 5, l = tid & 31;
    __shared__ __align__(16) float qs[DH];
    __shared__ int   cap_s[CC], dist_s[CC];
    __shared__ float cq_s[11], dq_s[3], wcap_s[11], wdist_s[3];
    __shared__ float logit_s[CC], attn_s[CC];

    qs[tid] = qt[(size_t)b * DH + tid];
    if (tid < CC) {
        cap_s[tid]  = caps[b * CC + tid];
        dist_s[tid] = dists[b * CC + tid];
    }
    __syncthreads();

    // table dots: warps 0..10 -> cq, 11..13 -> dq (raw; scaling later)
    if (w < 14) {
        const float* trow = (w < 11) ? cemb + w * DH : demb + (w - 11) * DH;
        float a = 0.f;
        #pragma unroll
        for (int i = l; i < DH; i += 32) a += trow[i] * qs[i];
        #pragma unroll
        for (int o = 16; o; o >>= 1) a += __shfl_xor_sync(0xffffffffu, a, o);
        if (l == 0) { if (w < 11) cq_s[w] = a; else dq_s[w - 11] = a; }
    }

    // raw row dots (default .ca loads: tile stays resident in L2 for gbar re-read)
    const float4* H4 = (const float4*)HtC + (size_t)b * (CC * DH / 4);
    const float4* q4 = (const float4*)qs;
    #pragma unroll
    for (int r = 0; r < 4; r++) {
        int c = w * 4 + r;
        const float4* hrow = H4 + c * 128;
        float acc = 0.f;
        #pragma unroll
        for (int j = 0; j < 4; j++) {
            int i = j * 32 + l;
            float4 h = hrow[i];
            acc += h.x * q4[i].x + h.y * q4[i].y + h.z * q4[i].z + h.w * q4[i].w;
        }
        #pragma unroll
        for (int o = 16; o; o >>= 1) acc += __shfl_xor_sync(0xffffffffu, acc, o);
        if (l == 0) logit_s[c] = acc;
    }
    __syncthreads();

    if (w == 0) {
        float x0 = (logit_s[l]      + cq_s[cap_s[l]]      + dq_s[dist_s[l]])      * SCALE;
        float x1 = (logit_s[l + 32] + cq_s[cap_s[l + 32]] + dq_s[dist_s[l + 32]]) * SCALE;
        float m = fmaxf(x0, x1);
        #pragma unroll
        for (int o = 16; o; o >>= 1) m = fmaxf(m, __shfl_xor_sync(0xffffffffu, m, o));
        float e0 = expf(x0 - m), e1 = expf(x1 - m);
        float s = e0 + e1;
        #pragma unroll
        for (int o = 16; o; o >>= 1) s += __shfl_xor_sync(0xffffffffu, s, o);
        float inv = 1.f / s;
        attn_s[l] = e0 * inv; attn_s[l + 32] = e1 * inv;
    }
    __syncthreads();

    // index-grouped attn weights
    if (tid < 11) {
        float s = 0.f;
        for (int c = 0; c < CC; c++) if (cap_s[c] == tid) s += attn_s[c];
        wcap_s[tid] = s;
    }
    if (tid >= 32 && tid < 35) {
        int u = tid - 32; float s = 0.f;
        for (int c = 0; c < CC; c++) if (dist_s[c] == u) s += attn_s[c];
        wdist_s[u] = s;
    }
    __syncthreads();

    // gbar over d = tid: all rows from L2, plus tables
    const float* Hb = HtC + (size_t)b * (CC * DH);
    float acc = 0.f;
    #pragma unroll 8
    for (int c = 0; c < CC; c++)
        acc = fmaf(attn_s[c], Hb[c * DH + tid], acc);
    #pragma unroll
    for (int v = 0; v < 11; v++)
        acc = fmaf(wcap_s[v], cemb[v * DH + tid], acc);
    #pragma unroll
    for (int u = 0; u < 3; u++)
        acc = fmaf(wdist_s[u], demb[u * DH + tid], acc);
    bf16 h, lo; split_bf16(acc, h, lo);
    gbh[(size_t)b * DH + tid] = h;
    gbl[(size_t)b * DH + tid] = lo;
}

// ---------------- fused pass 2: pure streaming dots + factored embeddings ----------------
__global__ void __launch_bounds__(512, 4) fused2_kernel(
    const float* __restrict__ HtC, const int* __restrict__ caps,
    const int* __restrict__ dists, const float* __restrict__ cemb,
    const float* __restrict__ demb, const float* __restrict__ kt,
    const void* __restrict__ dbl, float* __restrict__ out)
{
    int b = blockIdx.x, tid = threadIdx.x;
    int w = tid >> 5, l = tid & 31;
    __shared__ __align__(16) float ks[DH];
    __shared__ int   cap_s[CC], dist_s[CC];
    __shared__ float ck_s[11], dk_s[3];
    __shared__ float u_s[CC];

    ks[tid] = kt[(size_t)b * DH + tid];
    if (tid < CC) {
        cap_s[tid]  = caps[b * CC + tid];
        dist_s[tid] = dists[b * CC + tid];
    }
    __syncthreads();

    if (w < 14) {
        const float* trow = (w < 11) ? cemb + w * DH : demb + (w - 11) * DH;
        float a = 0.f;
        #pragma unroll
        for (int i = l; i < DH; i += 32) a += trow[i] * ks[i];
        #pragma unroll
        for (int o = 16; o; o >>= 1) a += __shfl_xor_sync(0xffffffffu, a, o);
        if (l == 0) { if (w < 11) ck_s[w] = a; else dk_s[w - 11] = a; }
    }

    const float4* H4 = (const float4*)HtC + (size_t)b * (CC * DH / 4);
    const float4* k4 = (const float4*)ks;
    #pragma unroll
    for (int r = 0; r < 4; r++) {
        int c = w * 4 + r;
        const float4* hrow = H4 + c * 128;
        float acc = 0.f;
        #pragma unroll
        for (int j = 0; j < 4; j++) {
            int i = j * 32 + l;
            float4 h = __ldcs(hrow + i);
            acc += h.x * k4[i].x + h.y * k4[i].y + h.z * k4[i].z + h.w * k4[i].w;
        }
        #pragma unroll
        for (int o = 16; o; o >>= 1) acc += __shfl_xor_sync(0xffffffffu, acc, o);
        if (l == 0) u_s[c] = acc;
    }
    __syncthreads();

    if (w == 0) {
        int dval = g_dbl_is_u8 ? (int)((const unsigned char*)dbl)[b]
                               : ((const int*)dbl)[b];
        int need = dval ? 2 : 1;
        float x0 = (u_s[l]      + ck_s[cap_s[l]]      + dk_s[dist_s[l]])      * SCALE;
        float x1 = (u_s[l + 32] + ck_s[cap_s[l + 32]] + dk_s[dist_s[l + 32]]) * SCALE;
        if (cap_s[l]      < need) x0 = __int_as_float(0xff800000);
        if (cap_s[l + 32] < need) x1 = __int_as_float(0xff800000);
        float m = fmaxf(x0, x1);
        #pragma unroll
        for (int o = 16; o; o >>= 1) m = fmaxf(m, __shfl_xor_sync(0xffffffffu, m, o));
        float e0 = expf(x0 - m), e1 = expf(x1 - m);
        float s = e0 + e1;
        #pragma unroll
        for (int o = 16; o; o >>= 1) s += __shfl_xor_sync(0xffffffffu, s, o);
        float inv = 1.f / s;
        out[(size_t)b * CC + l]      = e0 * inv;
        out[(size_t)b * CC + l + 32] = e1 * inv;
    }
}

extern "C" void kernel_launch(void* const* d_in, const int* in_sizes, int n_in,
                              void* d_out, int out_size) {
    const float* HtC   = (const float*)d_in[0];
    const int*   caps  = (const int*)  d_in[1];
    const int*   dists = (const int*)  d_in[2];
    const float* HX    = (const float*)d_in[3];
    const float* HS    = (const float*)d_in[4];
    const float* EQ    = (const float*)d_in[5];
    const void*  dbl   = d_in[6];
    const float* cemb  = (const float*)d_in[7];
    const float* demb  = (const float*)d_in[8];
    const float* Wq    = (const float*)d_in[9];
    const float* Wk    = (const float*)d_in[10];
    const float* Wv    = (const float*)d_in[11];
    float* out = (float*)d_out;

    bf16 *ctxh,*ctxl,*wbh,*wbl,*wkh,*wkl,*w1h,*w1l,*m2h,*m2l,*gbh,*gbl;
    float *qt,*kt;
    cudaGetSymbolAddress((void**)&ctxh, g_ctx_h);  cudaGetSymbolAddress((void**)&ctxl, g_ctx_l);
    cudaGetSymbolAddress((void**)&wbh,  g_WBT_h);  cudaGetSymbolAddress((void**)&wbl,  g_WBT_l);
    cudaGetSymbolAddress((void**)&wkh,  g_WkT_h);  cudaGetSymbolAddress((void**)&wkl,  g_WkT_l);
    cudaGetSymbolAddress((void**)&w1h,  g_W1t_h);  cudaGetSymbolAddress((void**)&w1l,  g_W1t_l);
    cudaGetSymbolAddress((void**)&m2h,  g_M2t_h);  cudaGetSymbolAddress((void**)&m2l,  g_M2t_l);
    cudaGetSymbolAddress((void**)&gbh,  g_gbar_h); cudaGetSymbolAddress((void**)&gbl,  g_gbar_l);
    cudaGetSymbolAddress((void**)&qt,   g_qt);     cudaGetSymbolAddress((void**)&kt,   g_kt);

    cudaFuncSetAttribute(mma_gemm_kernel<0>, cudaFuncAttributeMaxDynamicSharedMemorySize, MG_SMEM);
    cudaFuncSetAttribute(mma_gemm_kernel<2>, cudaFuncAttributeMaxDynamicSharedMemorySize, MG_SMEM);

    // 1) prep: weight transposes (B concat) + context pack/split + dtype sniff
    prep_kernel<<<4353, 256>>>(Wq, Wk, Wv, wbh, wbl, wkh, wkl,
                               (uint2*)ctxh, (uint2*)ctxl,
                               (const float4*)HX, (const float4*)HS, (const float4*)EQ,
                               (const unsigned char*)dbl);
    // 2) fold (merged): D[d, 0..2047] = sum_e WkT[d,e]*WBT[n,e] -> W1t | M2t
    mma_gemm_kernel<2><<<dim3(NB2/64, DH/64), 128, MG_SMEM>>>(
        nullptr, w1h, w1l, m2h, m2l, wkh, wkl, wbh, wbl, NB2, DH);
    // 3) qt[b,d] = sum_i ctx[b,i]*W1t[d,i]    (M=2048, N=512, K=1536)
    mma_gemm_kernel<0><<<dim3(DH/64, BB/64), 128, MG_SMEM>>>(
        qt, nullptr, nullptr, nullptr, nullptr, ctxh, ctxl, w1h, w1l, DH, K3);
    // 4) logits/softmax/gbar (no tile; L2 re-read; 4 CTAs/SM via launch_bounds)
    fused1_kernel<<<BB, 512>>>(HtC, caps, dists, cemb, demb, qt, gbh, gbl);
    // 5) kt[b,d] = sum_e2 gbar[b,e2]*M2t[d,e2] (M=2048, N=512, K=512)
    mma_gemm_kernel<0><<<dim3(DH/64, BB/64), 128, MG_SMEM>>>(
        kt, nullptr, nullptr, nullptr, nullptr, gbh, gbl, m2h, m2l, DH, DH);
    // 6) u/mask/softmax -> out (streaming, factored embeddings)
    fused2_kernel<<<BB, 512>>>(HtC, caps, dists, cemb, demb, kt, dbl, out);
}

// round 12
// speedup vs baseline: 1.0460x; 1.0103x over previous
#include <cuda_runtime.h>
#include <cuda_bf16.h>
#include <math.h>
#include <stdint.h>

// Problem constants
#define BB   2048
#define CC   64
#define DH   512
#define K3   1536
#define NB2  (K3 + DH)                 // concat fold-B rows
#define SCALE 0.044194173824159216f   // 1/sqrt(512)

typedef unsigned long long u64;
typedef __nv_bfloat16 bf16;

// ---------------- scratch (static device globals) ----------------
__device__ bf16  g_ctx_h [BB * K3];
__device__ bf16  g_ctx_l [BB * K3];
__device__ bf16  g_WBT_h [NB2 * DH];  // rows 0..1535: WqT[i,e]; rows 1536..2047: WvT[e2,e]
__device__ bf16  g_WBT_l [NB2 * DH];
__device__ bf16  g_WkT_h [DH * DH];
__device__ bf16  g_WkT_l [DH * DH];
__device__ bf16  g_W1t_h [DH * K3];   // W1t[d,i] = sum_e WkT[d,e]*WqT[i,e]
__device__ bf16  g_W1t_l [DH * K3];
__device__ bf16  g_M2t_h [DH * DH];   // M2t[d,e2] = sum_e WkT[d,e]*WvT[e2,e]
__device__ bf16  g_M2t_l [DH * DH];
__device__ float g_qt    [BB * DH];
__device__ bf16  g_gbar_h[BB * DH];
__device__ bf16  g_gbar_l[BB * DH];
__device__ float g_kt    [BB * DH];
__device__ int   g_dbl_is_u8;

// ---------------- helpers ----------------
__device__ __forceinline__ uint32_t smem_u32(const void* p) {
    uint32_t a;
    asm("{ .reg .u64 t; cvta.to.shared.u64 t, %1; cvt.u32.u64 %0, t; }" : "=r"(a) : "l"(p));
    return a;
}
__device__ __forceinline__ void cp_async16(uint32_t dst, const void* src) {
    asm volatile("cp.async.cg.shared.global [%0], [%1], 16;" :: "r"(dst), "l"(src) : "memory");
}
__device__ __forceinline__ void cp_commit() {
    asm volatile("cp.async.commit_group;" ::: "memory");
}
__device__ __forceinline__ void split_bf16(float f, bf16& h, bf16& l) {
    h = __float2bfloat16_rn(f);
    l = __float2bfloat16_rn(f - __bfloat162float(h));
}
__device__ __forceinline__ void mma_bf16(float* c, const uint32_t* a, const uint32_t* b) {
    asm volatile(
        "mma.sync.aligned.m16n8k16.row.col.f32.bf16.bf16.f32 "
        "{%0,%1,%2,%3}, {%4,%5,%6,%7}, {%8,%9}, {%0,%1,%2,%3};"
        : "+f"(c[0]), "+f"(c[1]), "+f"(c[2]), "+f"(c[3])
        : "r"(a[0]), "r"(a[1]), "r"(a[2]), "r"(a[3]), "r"(b[0]), "r"(b[1]));
}
__device__ __forceinline__ void ldmx4(uint32_t* r, uint32_t saddr) {
    asm volatile("ldmatrix.sync.aligned.m8n8.x4.shared.b16 {%0,%1,%2,%3}, [%4];"
        : "=r"(r[0]), "=r"(r[1]), "=r"(r[2]), "=r"(r[3]) : "r"(saddr));
}

// ---------------- prep: transposes+splits, context pack, dtype sniff ----------------
__global__ void prep_kernel(const float* __restrict__ Wq,
                            const float* __restrict__ Wk,
                            const float* __restrict__ Wv,
                            bf16* __restrict__ wbh, bf16* __restrict__ wbl,
                            bf16* __restrict__ wkh, bf16* __restrict__ wkl,
                            uint2* __restrict__ ch, uint2* __restrict__ cl,
                            const float4* __restrict__ hx,
                            const float4* __restrict__ hs,
                            const float4* __restrict__ eq,
                            const unsigned char* __restrict__ dblp) {
    int bid = blockIdx.x;
    if (bid == 1280) {
        __shared__ int any;
        if (threadIdx.x == 0) any = 0;
        __syncthreads();
        int found = 0;
        for (int i = threadIdx.x; i < 2048; i += 256)
            if ((i & 3) && dblp[i]) found = 1;
        if (found) any = 1;
        __syncthreads();
        if (threadIdx.x == 0) g_dbl_is_u8 = any;
        return;
    }
    if (bid > 1280) {
        int idx = (bid - 1281) * 256 + threadIdx.x;   // BB*384 float4s
        int b = idx / 384;
        int r = idx - b * 384;
        float4 v;
        if (r < 128)       v = hx[b * 128 + r];
        else if (r < 256)  v = hs[b * 128 + (r - 128)];
        else               v = eq[b * 128 + (r - 256)];
        bf16 h0,l0,h1,l1,h2,l2,h3,l3;
        split_bf16(v.x,h0,l0); split_bf16(v.y,h1,l1);
        split_bf16(v.z,h2,l2); split_bf16(v.w,h3,l3);
        __nv_bfloat162 H01 = {h0,h1}, H23 = {h2,h3}, L01 = {l0,l1}, L23 = {l2,l3};
        ch[idx] = make_uint2(*(uint32_t*)&H01, *(uint32_t*)&H23);
        cl[idx] = make_uint2(*(uint32_t*)&L01, *(uint32_t*)&L23);
        return;
    }
    int tx = threadIdx.x & 31, ty = threadIdx.x >> 5;   // 32 x 8
    const float* in; bf16 *oh, *ol; int Cn, bx, by, roff;
    if (bid < 768)       { in = Wq; oh = wbh; ol = wbl; Cn = K3; bx = bid % 48;          by = bid / 48;         roff = 0; }
    else if (bid < 1024) { in = Wk; oh = wkh; ol = wkl; Cn = DH; bx = (bid - 768) & 15;  by = (bid - 768) >> 4; roff = 0; }
    else                 { in = Wv; oh = wbh; ol = wbl; Cn = DH; bx = (bid - 1024) & 15; by = (bid - 1024) >> 4; roff = K3; }
    __shared__ float t[32][33];
    int i0 = bx * 32, e0 = by * 32;
    #pragma unroll
    for (int j = 0; j < 32; j += 8)
        t[ty + j][tx] = in[(size_t)(e0 + ty + j) * Cn + i0 + tx];
    __syncthreads();
    #pragma unroll
    for (int j = 0; j < 32; j += 8) {
        float f = t[tx][ty + j];
        bf16 h, l; split_bf16(f, h, l);
        size_t o = (size_t)(roff + i0 + ty + j) * DH + e0 + tx;
        oh[o] = h; ol[o] = l;
    }
}

// ---------------- mma.sync GEMM (R7 config) ----------------
#define MG_AH   0
#define MG_AL   5120
#define MG_BH   10240
#define MG_BL   15360
#define MG_STG  20480
#define MG_SMEM (3 * MG_STG)

template<int MODE>
__global__ void __launch_bounds__(128, 2) mma_gemm_kernel(
    float* __restrict__ outf,
    bf16* __restrict__ o1h, bf16* __restrict__ o1l,
    bf16* __restrict__ o2h, bf16* __restrict__ o2l,
    const bf16* __restrict__ Ah, const bf16* __restrict__ Al,
    const bf16* __restrict__ Bh, const bf16* __restrict__ Bl,
    int N, int K)
{
    extern __shared__ char dsm[];
    uint32_t sb0 = smem_u32(dsm);

    int tid = threadIdx.x;
    int lane = tid & 31, wid = tid >> 5;
    int wm = wid & 1, wn = wid >> 1;
    int gid = lane >> 2, tid4 = lane & 3;
    int lr = lane & 7, sel = lane >> 3;
    int bm = blockIdx.y * 64, bn = blockIdx.x * 64;
    int KB = K >> 5;

    uint32_t a_row    = (uint32_t)(wm * 32 + lr + (sel & 1) * 8);
    uint32_t a_coloff = (uint32_t)((sel >> 1) * 8);
    uint32_t b_row    = (uint32_t)(wn * 32 + lr + (sel >> 1) * 8);
    uint32_t b_coloff = (uint32_t)((sel & 1) * 8);

    float C[2][4][4];
    #pragma unroll
    for (int t = 0; t < 2; t++)
        #pragma unroll
        for (int j = 0; j < 4; j++)
            #pragma unroll
            for (int q = 0; q < 4; q++) C[t][j][q] = 0.f;

    auto load_stage = [&](int kb, int s) {
        uint32_t sb = sb0 + s * MG_STG;
        int ko = kb * 32;
        #pragma unroll
        for (int i = 0; i < 8; i++) {
            int v = tid + i * 128;
            if (v < 256) {
                int r = v >> 2, c = v & 3;
                cp_async16(sb + MG_AH + r * 80 + c * 16,
                           Ah + (size_t)(bm + r) * K + ko + c * 8);
            } else if (v < 512) {
                int u = v - 256; int r = u >> 2, c = u & 3;
                cp_async16(sb + MG_AL + r * 80 + c * 16,
                           Al + (size_t)(bm + r) * K + ko + c * 8);
            } else if (v < 768) {
                int u = v - 512; int r = u >> 2, c = u & 3;
                cp_async16(sb + MG_BH + r * 80 + c * 16,
                           Bh + (size_t)(bn + r) * K + ko + c * 8);
            } else {
                int u = v - 768; int r = u >> 2, c = u & 3;
                cp_async16(sb + MG_BL + r * 80 + c * 16,
                           Bl + (size_t)(bn + r) * K + ko + c * 8);
            }
        }
        cp_commit();
    };

    load_stage(0, 0);
    if (KB > 1) load_stage(1, 1);

    for (int kb = 0; kb < KB; kb++) {
        if (kb + 2 < KB) {
            load_stage(kb + 2, (kb + 2) % 3);
            asm volatile("cp.async.wait_group 2;" ::: "memory");
        } else if (kb + 1 < KB) {
            asm volatile("cp.async.wait_group 1;" ::: "memory");
        } else {
            asm volatile("cp.async.wait_group 0;" ::: "memory");
        }
        __syncthreads();

        uint32_t st = sb0 + (kb % 3) * MG_STG;
        #pragma unroll
        for (int step = 0; step < 2; step++) {
            int kbase = step * 16;
            uint32_t ah[2][4], al[2][4], bh[8], bl[8];
            #pragma unroll
            for (int t = 0; t < 2; t++) {
                uint32_t aa = st + MG_AH + (a_row + t * 16) * 80 + (kbase + a_coloff) * 2;
                ldmx4(ah[t], aa);
                ldmx4(al[t], aa + (MG_AL - MG_AH));
            }
            #pragma unroll
            for (int jp = 0; jp < 2; jp++) {
                uint32_t ba = st + MG_BH + (b_row + jp * 16) * 80 + (kbase + b_coloff) * 2;
                ldmx4(&bh[jp * 4], ba);
                ldmx4(&bl[jp * 4], ba + (MG_BL - MG_BH));
            }
            #pragma unroll
            for (int t = 0; t < 2; t++)
                #pragma unroll
                for (int j = 0; j < 4; j++) {
                    mma_bf16(C[t][j], ah[t], &bh[j * 2]);
                    mma_bf16(C[t][j], ah[t], &bl[j * 2]);
                    mma_bf16(C[t][j], al[t], &bh[j * 2]);
                }
        }
        __syncthreads();
    }

    bf16 *ph = o1h, *pl = o1l;
    int nstride = K3, coff = 0;
    if (MODE == 2 && bn >= K3) { ph = o2h; pl = o2l; nstride = DH; coff = K3; }
    #pragma unroll
    for (int t = 0; t < 2; t++) {
        int m0 = bm + wm * 32 + t * 16 + gid;
        #pragma unroll
        for (int j = 0; j < 4; j++) {
            int col = bn + wn * 32 + j * 8 + tid4 * 2;
            if (MODE == 2) {
                bf16 h0,l0,h1,l1;
                split_bf16(C[t][j][0], h0, l0); split_bf16(C[t][j][1], h1, l1);
                __nv_bfloat162 H = {h0,h1}, L = {l0,l1};
                *(uint32_t*)(ph + (size_t)m0 * nstride + col - coff) = *(uint32_t*)&H;
                *(uint32_t*)(pl + (size_t)m0 * nstride + col - coff) = *(uint32_t*)&L;
                split_bf16(C[t][j][2], h0, l0); split_bf16(C[t][j][3], h1, l1);
                __nv_bfloat162 H2 = {h0,h1}, L2 = {l0,l1};
                *(uint32_t*)(ph + (size_t)(m0 + 8) * nstride + col - coff) = *(uint32_t*)&H2;
                *(uint32_t*)(pl + (size_t)(m0 + 8) * nstride + col - coff) = *(uint32_t*)&L2;
            } else {
                *(float2*)(outf + (size_t)m0 * N + col)       = make_float2(C[t][j][0], C[t][j][1]);
                *(float2*)(outf + (size_t)(m0 + 8) * N + col) = make_float2(C[t][j][2], C[t][j][3]);
            }
        }
    }
}

// ---------------- fused pass 1: MLP-restructured dots + factored embeddings ----------------
__global__ void __launch_bounds__(512, 4) fused1_kernel(
    const float* __restrict__ HtC, const int* __restrict__ caps,
    const int* __restrict__ dists, const float* __restrict__ cemb,
    const float* __restrict__ demb, const float* __restrict__ qt,
    bf16* __restrict__ gbh, bf16* __restrict__ gbl)
{
    int b = blockIdx.x, tid = threadIdx.x;
    int w = tid >> 5, l = tid & 31;
    __shared__ __align__(16) float qs[DH];
    __shared__ int   cap_s[CC], dist_s[CC];
    __shared__ float cq_s[11], dq_s[3], wcap_s[11], wdist_s[3];
    __shared__ float logit_s[CC], attn_s[CC];

    qs[tid] = qt[(size_t)b * DH + tid];
    if (tid < CC) {
        cap_s[tid]  = caps[b * CC + tid];
        dist_s[tid] = dists[b * CC + tid];
    }
    __syncthreads();

    // table dots: warps 0..10 -> cq, 11..13 -> dq (raw; scaling later)
    if (w < 14) {
        const float* trow = (w < 11) ? cemb + w * DH : demb + (w - 11) * DH;
        float a = 0.f;
        #pragma unroll
        for (int i = l; i < DH; i += 32) a += trow[i] * qs[i];
        #pragma unroll
        for (int o = 16; o; o >>= 1) a += __shfl_xor_sync(0xffffffffu, a, o);
        if (l == 0) { if (w < 11) cq_s[w] = a; else dq_s[w - 11] = a; }
    }

    // row dots: 4 independent accumulators, NO shfl between rows (max MLP),
    // interleaved reductions at the end.
    const float4* H4 = (const float4*)HtC + (size_t)b * (CC * DH / 4);
    const float4* q4 = (const float4*)qs;
    float accr[4];
    #pragma unroll
    for (int r = 0; r < 4; r++) {
        const float4* hrow = H4 + (w * 4 + r) * 128;
        float acc = 0.f;
        #pragma unroll
        for (int j = 0; j < 4; j++) {
            int i = j * 32 + l;
            float4 h = hrow[i], q = q4[i];
            acc += h.x * q.x + h.y * q.y + h.z * q.z + h.w * q.w;
        }
        accr[r] = acc;
    }
    #pragma unroll
    for (int o = 16; o; o >>= 1) {
        accr[0] += __shfl_xor_sync(0xffffffffu, accr[0], o);
        accr[1] += __shfl_xor_sync(0xffffffffu, accr[1], o);
        accr[2] += __shfl_xor_sync(0xffffffffu, accr[2], o);
        accr[3] += __shfl_xor_sync(0xffffffffu, accr[3], o);
    }
    if (l == 0) {
        logit_s[w * 4 + 0] = accr[0];
        logit_s[w * 4 + 1] = accr[1];
        logit_s[w * 4 + 2] = accr[2];
        logit_s[w * 4 + 3] = accr[3];
    }
    __syncthreads();

    if (w == 0) {
        float x0 = (logit_s[l]      + cq_s[cap_s[l]]      + dq_s[dist_s[l]])      * SCALE;
        float x1 = (logit_s[l + 32] + cq_s[cap_s[l + 32]] + dq_s[dist_s[l + 32]]) * SCALE;
        float m = fmaxf(x0, x1);
        #pragma unroll
        for (int o = 16; o; o >>= 1) m = fmaxf(m, __shfl_xor_sync(0xffffffffu, m, o));
        float e0 = expf(x0 - m), e1 = expf(x1 - m);
        float s = e0 + e1;
        #pragma unroll
        for (int o = 16; o; o >>= 1) s += __shfl_xor_sync(0xffffffffu, s, o);
        float inv = 1.f / s;
        attn_s[l] = e0 * inv; attn_s[l + 32] = e1 * inv;
    }
    __syncthreads();

    // index-grouped attn weights
    if (tid < 11) {
        float s = 0.f;
        for (int c = 0; c < CC; c++) if (cap_s[c] == tid) s += attn_s[c];
        wcap_s[tid] = s;
    }
    if (tid >= 32 && tid < 35) {
        int u = tid - 32; float s = 0.f;
        for (int c = 0; c < CC; c++) if (dist_s[c] == u) s += attn_s[c];
        wdist_s[u] = s;
    }
    __syncthreads();

    // gbar over d = tid: 4 partial accumulators break the FMA chain
    const float* Hb = HtC + (size_t)b * (CC * DH);
    float a0 = 0.f, a1 = 0.f, a2 = 0.f, a3 = 0.f;
    #pragma unroll 4
    for (int c = 0; c < CC; c += 4) {
        a0 = fmaf(attn_s[c + 0], Hb[(c + 0) * DH + tid], a0);
        a1 = fmaf(attn_s[c + 1], Hb[(c + 1) * DH + tid], a1);
        a2 = fmaf(attn_s[c + 2], Hb[(c + 2) * DH + tid], a2);
        a3 = fmaf(attn_s[c + 3], Hb[(c + 3) * DH + tid], a3);
    }
    float acc = (a0 + a1) + (a2 + a3);
    #pragma unroll
    for (int v = 0; v < 11; v++)
        acc = fmaf(wcap_s[v], cemb[v * DH + tid], acc);
    #pragma unroll
    for (int u = 0; u < 3; u++)
        acc = fmaf(wdist_s[u], demb[u * DH + tid], acc);
    bf16 h, lo; split_bf16(acc, h, lo);
    gbh[(size_t)b * DH + tid] = h;
    gbl[(size_t)b * DH + tid] = lo;
}

// ---------------- fused pass 2: MLP-restructured streaming dots ----------------
__global__ void __launch_bounds__(512, 4) fused2_kernel(
    const float* __restrict__ HtC, const int* __restrict__ caps,
    const int* __restrict__ dists, const float* __restrict__ cemb,
    const float* __restrict__ demb, const float* __restrict__ kt,
    const void* __restrict__ dbl, float* __restrict__ out)
{
    int b = blockIdx.x, tid = threadIdx.x;
    int w = tid >> 5, l = tid & 31;
    __shared__ __align__(16) float ks[DH];
    __shared__ int   cap_s[CC], dist_s[CC];
    __shared__ float ck_s[11], dk_s[3];
    __shared__ float u_s[CC];

    ks[tid] = kt[(size_t)b * DH + tid];
    if (tid < CC) {
        cap_s[tid]  = caps[b * CC + tid];
        dist_s[tid] = dists[b * CC + tid];
    }
    __syncthreads();

    if (w < 14) {
        const float* trow = (w < 11) ? cemb + w * DH : demb + (w - 11) * DH;
        float a = 0.f;
        #pragma unroll
        for (int i = l; i < DH; i += 32) a += trow[i] * ks[i];
        #pragma unroll
        for (int o = 16; o; o >>= 1) a += __shfl_xor_sync(0xffffffffu, a, o);
        if (l == 0) { if (w < 11) ck_s[w] = a; else dk_s[w - 11] = a; }
    }

    const float4* H4 = (const float4*)HtC + (size_t)b * (CC * DH / 4);
    const float4* k4 = (const float4*)ks;
    float accr[4];
    #pragma unroll
    for (int r = 0; r < 4; r++) {
        const float4* hrow = H4 + (w * 4 + r) * 128;
        float acc = 0.f;
        #pragma unroll
        for (int j = 0; j < 4; j++) {
            int i = j * 32 + l;
            float4 h = __ldcs(hrow + i);
            float4 q = k4[i];
            acc += h.x * q.x + h.y * q.y + h.z * q.z + h.w * q.w;
        }
        accr[r] = acc;
    }
    #pragma unroll
    for (int o = 16; o; o >>= 1) {
        accr[0] += __shfl_xor_sync(0xffffffffu, accr[0], o);
        accr[1] += __shfl_xor_sync(0xffffffffu, accr[1], o);
        accr[2] += __shfl_xor_sync(0xffffffffu, accr[2], o);
        accr[3] += __shfl_xor_sync(0xffffffffu, accr[3], o);
    }
    if (l == 0) {
        u_s[w * 4 + 0] = accr[0];
        u_s[w * 4 + 1] = accr[1];
        u_s[w * 4 + 2] = accr[2];
        u_s[w * 4 + 3] = accr[3];
    }
    __syncthreads();

    if (w == 0) {
        int dval = g_dbl_is_u8 ? (int)((const unsigned char*)dbl)[b]
                               : ((const int*)dbl)[b];
        int need = dval ? 2 : 1;
        float x0 = (u_s[l]      + ck_s[cap_s[l]]      + dk_s[dist_s[l]])      * SCALE;
        float x1 = (u_s[l + 32] + ck_s[cap_s[l + 32]] + dk_s[dist_s[l + 32]]) * SCALE;
        if (cap_s[l]      < need) x0 = __int_as_float(0xff800000);
        if (cap_s[l + 32] < need) x1 = __int_as_float(0xff800000);
        float m = fmaxf(x0, x1);
        #pragma unroll
        for (int o = 16; o; o >>= 1) m = fmaxf(m, __shfl_xor_sync(0xffffffffu, m, o));
        float e0 = expf(x0 - m), e1 = expf(x1 - m);
        float s = e0 + e1;
        #pragma unroll
        for (int o = 16; o; o >>= 1) s += __shfl_xor_sync(0xffffffffu, s, o);
        float inv = 1.f / s;
        out[(size_t)b * CC + l]      = e0 * inv;
        out[(size_t)b * CC + l + 32] = e1 * inv;
    }
}

extern "C" void kernel_launch(void* const* d_in, const int* in_sizes, int n_in,
                              void* d_out, int out_size) {
    const float* HtC   = (const float*)d_in[0];
    const int*   caps  = (const int*)  d_in[1];
    const int*   dists = (const int*)  d_in[2];
    const float* HX    = (const float*)d_in[3];
    const float* HS    = (const float*)d_in[4];
    const float* EQ    = (const float*)d_in[5];
    const void*  dbl   = d_in[6];
    const float* cemb  = (const float*)d_in[7];
    const float* demb  = (const float*)d_in[8];
    const float* Wq    = (const float*)d_in[9];
    const float* Wk    = (const float*)d_in[10];
    const float* Wv    = (const float*)d_in[11];
    float* out = (float*)d_out;

    bf16 *ctxh,*ctxl,*wbh,*wbl,*wkh,*wkl,*w1h,*w1l,*m2h,*m2l,*gbh,*gbl;
    float *qt,*kt;
    cudaGetSymbolAddress((void**)&ctxh, g_ctx_h);  cudaGetSymbolAddress((void**)&ctxl, g_ctx_l);
    cudaGetSymbolAddress((void**)&wbh,  g_WBT_h);  cudaGetSymbolAddress((void**)&wbl,  g_WBT_l);
    cudaGetSymbolAddress((void**)&wkh,  g_WkT_h);  cudaGetSymbolAddress((void**)&wkl,  g_WkT_l);
    cudaGetSymbolAddress((void**)&w1h,  g_W1t_h);  cudaGetSymbolAddress((void**)&w1l,  g_W1t_l);
    cudaGetSymbolAddress((void**)&m2h,  g_M2t_h);  cudaGetSymbolAddress((void**)&m2l,  g_M2t_l);
    cudaGetSymbolAddress((void**)&gbh,  g_gbar_h); cudaGetSymbolAddress((void**)&gbl,  g_gbar_l);
    cudaGetSymbolAddress((void**)&qt,   g_qt);     cudaGetSymbolAddress((void**)&kt,   g_kt);

    cudaFuncSetAttribute(mma_gemm_kernel<0>, cudaFuncAttributeMaxDynamicSharedMemorySize, MG_SMEM);
    cudaFuncSetAttribute(mma_gemm_kernel<2>, cudaFuncAttributeMaxDynamicSharedMemorySize, MG_SMEM);

    // 1) prep: weight transposes (B concat) + context pack/split + dtype sniff
    prep_kernel<<<4353, 256>>>(Wq, Wk, Wv, wbh, wbl, wkh, wkl,
                               (uint2*)ctxh, (uint2*)ctxl,
                               (const float4*)HX, (const float4*)HS, (const float4*)EQ,
                               (const unsigned char*)dbl);
    // 2) fold (merged): D[d, 0..2047] = sum_e WkT[d,e]*WBT[n,e] -> W1t | M2t
    mma_gemm_kernel<2><<<dim3(NB2/64, DH/64), 128, MG_SMEM>>>(
        nullptr, w1h, w1l, m2h, m2l, wkh, wkl, wbh, wbl, NB2, DH);
    // 3) qt[b,d] = sum_i ctx[b,i]*W1t[d,i]    (M=2048, N=512, K=1536)
    mma_gemm_kernel<0><<<dim3(DH/64, BB/64), 128, MG_SMEM>>>(
        qt, nullptr, nullptr, nullptr, nullptr, ctxh, ctxl, w1h, w1l, DH, K3);
    // 4) logits/softmax/gbar (restructured MLP)
    fused1_kernel<<<BB, 512>>>(HtC, caps, dists, cemb, demb, qt, gbh, gbl);
    // 5) kt[b,d] = sum_e2 gbar[b,e2]*M2t[d,e2] (M=2048, N=512, K=512)
    mma_gemm_kernel<0><<<dim3(DH/64, BB/64), 128, MG_SMEM>>>(
        kt, nullptr, nullptr, nullptr, nullptr, gbh, gbl, m2h, m2l, DH, DH);
    // 6) u/mask/softmax -> out (restructured MLP)
    fused2_kernel<<<BB, 512>>>(HtC, caps, dists, cemb, demb, kt, dbl, out);
}

// round 14
// speedup vs baseline: 1.1240x; 1.0745x over previous
#include <cuda_runtime.h>
#include <cuda_bf16.h>
#include <math.h>
#include <stdint.h>

// Problem constants
#define BB   2048
#define CC   64
#define DH   512
#define K3   1536
#define NB2  (K3 + DH)                 // concat fold-B rows
#define SCALE 0.044194173824159216f   // 1/sqrt(512)

typedef unsigned long long u64;
typedef __nv_bfloat16 bf16;

// ---------------- scratch (static device globals) ----------------
__device__ bf16  g_ctx_h [BB * K3];
__device__ bf16  g_ctx_l [BB * K3];
__device__ bf16  g_WBT_h [NB2 * DH];  // rows 0..1535: WqT[i,e]; rows 1536..2047: WvT[e2,e]
__device__ bf16  g_WBT_l [NB2 * DH];
__device__ bf16  g_WkT_h [DH * DH];
__device__ bf16  g_WkT_l [DH * DH];
__device__ bf16  g_W1t_h [DH * K3];   // W1t[d,i] = sum_e WkT[d,e]*WqT[i,e]
__device__ bf16  g_W1t_l [DH * K3];
__device__ bf16  g_M2t_h [DH * DH];   // M2t[d,e2] = sum_e WkT[d,e]*WvT[e2,e]
__device__ bf16  g_M2t_l [DH * DH];
__device__ float g_qt    [BB * DH];
__device__ bf16  g_gbar_h[BB * DH];
__device__ bf16  g_gbar_l[BB * DH];
__device__ float g_kt    [BB * DH];
__device__ int   g_dbl_is_u8;

// ---------------- helpers ----------------
__device__ __forceinline__ uint32_t smem_u32(const void* p) {
    uint32_t a;
    asm("{ .reg .u64 t; cvta.to.shared.u64 t, %1; cvt.u32.u64 %0, t; }" : "=r"(a) : "l"(p));
    return a;
}
__device__ __forceinline__ void cp_async16(uint32_t dst, const void* src) {
    asm volatile("cp.async.cg.shared.global [%0], [%1], 16;" :: "r"(dst), "l"(src) : "memory");
}
__device__ __forceinline__ void cp_commit() {
    asm volatile("cp.async.commit_group;" ::: "memory");
}
__device__ __forceinline__ void split_bf16(float f, bf16& h, bf16& l) {
    h = __float2bfloat16_rn(f);
    l = __float2bfloat16_rn(f - __bfloat162float(h));
}
__device__ __forceinline__ void mma_bf16(float* c, const uint32_t* a, const uint32_t* b) {
    asm volatile(
        "mma.sync.aligned.m16n8k16.row.col.f32.bf16.bf16.f32 "
        "{%0,%1,%2,%3}, {%4,%5,%6,%7}, {%8,%9}, {%0,%1,%2,%3};"
        : "+f"(c[0]), "+f"(c[1]), "+f"(c[2]), "+f"(c[3])
        : "r"(a[0]), "r"(a[1]), "r"(a[2]), "r"(a[3]), "r"(b[0]), "r"(b[1]));
}
__device__ __forceinline__ void ldmx4(uint32_t* r, uint32_t saddr) {
    asm volatile("ldmatrix.sync.aligned.m8n8.x4.shared.b16 {%0,%1,%2,%3}, [%4];"
        : "=r"(r[0]), "=r"(r[1]), "=r"(r[2]), "=r"(r[3]) : "r"(saddr));
}

// ---------------- prep: transposes+splits, context pack, dtype sniff ----------------
__global__ void prep_kernel(const float* __restrict__ Wq,
                            const float* __restrict__ Wk,
                            const float* __restrict__ Wv,
                            bf16* __restrict__ wbh, bf16* __restrict__ wbl,
                            bf16* __restrict__ wkh, bf16* __restrict__ wkl,
                            uint2* __restrict__ ch, uint2* __restrict__ cl,
                            const float4* __restrict__ hx,
                            const float4* __restrict__ hs,
                            const float4* __restrict__ eq,
                            const unsigned char* __restrict__ dblp) {
    int bid = blockIdx.x;
    if (bid == 1280) {
        __shared__ int any;
        if (threadIdx.x == 0) any = 0;
        __syncthreads();
        int found = 0;
        for (int i = threadIdx.x; i < 2048; i += 256)
            if ((i & 3) && dblp[i]) found = 1;
        if (found) any = 1;
        __syncthreads();
        if (threadIdx.x == 0) g_dbl_is_u8 = any;
        return;
    }
    if (bid > 1280) {
        int idx = (bid - 1281) * 256 + threadIdx.x;   // BB*384 float4s
        int b = idx / 384;
        int r = idx - b * 384;
        float4 v;
        if (r < 128)       v = hx[b * 128 + r];
        else if (r < 256)  v = hs[b * 128 + (r - 128)];
        else               v = eq[b * 128 + (r - 256)];
        bf16 h0,l0,h1,l1,h2,l2,h3,l3;
        split_bf16(v.x,h0,l0); split_bf16(v.y,h1,l1);
        split_bf16(v.z,h2,l2); split_bf16(v.w,h3,l3);
        __nv_bfloat162 H01 = {h0,h1}, H23 = {h2,h3}, L01 = {l0,l1}, L23 = {l2,l3};
        ch[idx] = make_uint2(*(uint32_t*)&H01, *(uint32_t*)&H23);
        cl[idx] = make_uint2(*(uint32_t*)&L01, *(uint32_t*)&L23);
        return;
    }
    int tx = threadIdx.x & 31, ty = threadIdx.x >> 5;   // 32 x 8
    const float* in; bf16 *oh, *ol; int Cn, bx, by, roff;
    if (bid < 768)       { in = Wq; oh = wbh; ol = wbl; Cn = K3; bx = bid % 48;          by = bid / 48;         roff = 0; }
    else if (bid < 1024) { in = Wk; oh = wkh; ol = wkl; Cn = DH; bx = (bid - 768) & 15;  by = (bid - 768) >> 4; roff = 0; }
    else                 { in = Wv; oh = wbh; ol = wbl; Cn = DH; bx = (bid - 1024) & 15; by = (bid - 1024) >> 4; roff = K3; }
    __shared__ float t[32][33];
    int i0 = bx * 32, e0 = by * 32;
    #pragma unroll
    for (int j = 0; j < 32; j += 8)
        t[ty + j][tx] = in[(size_t)(e0 + ty + j) * Cn + i0 + tx];
    __syncthreads();
    #pragma unroll
    for (int j = 0; j < 32; j += 8) {
        float f = t[tx][ty + j];
        bf16 h, l; split_bf16(f, h, l);
        size_t o = (size_t)(roff + i0 + ty + j) * DH + e0 + tx;
        oh[o] = h; ol[o] = l;
    }
}

// ---------------- mma.sync GEMM: BK=64, 2-stage (fewer syncs) ----------------
// CTA 64x64, 128 threads (2M x 2N warps, warp tile 32x32).
// Stage: 4 tiles x 64 rows x 144B pitch (128B data + 16B pad).
#define MG_PITCH 144
#define MG_AH   0
#define MG_AL   9216
#define MG_BH   18432
#define MG_BL   27648
#define MG_STG  36864
#define MG_SMEM (2 * MG_STG)

template<int MODE>
__global__ void __launch_bounds__(128, 2) mma_gemm_kernel(
    float* __restrict__ outf,
    bf16* __restrict__ o1h, bf16* __restrict__ o1l,
    bf16* __restrict__ o2h, bf16* __restrict__ o2l,
    const bf16* __restrict__ Ah, const bf16* __restrict__ Al,
    const bf16* __restrict__ Bh, const bf16* __restrict__ Bl,
    int N, int K)
{
    extern __shared__ char dsm[];
    uint32_t sb0 = smem_u32(dsm);

    int tid = threadIdx.x;
    int lane = tid & 31, wid = tid >> 5;
    int wm = wid & 1, wn = wid >> 1;
    int gid = lane >> 2, tid4 = lane & 3;
    int lr = lane & 7, sel = lane >> 3;
    int bm = blockIdx.y * 64, bn = blockIdx.x * 64;
    int KB = K >> 6;

    uint32_t a_row    = (uint32_t)(wm * 32 + lr + (sel & 1) * 8);
    uint32_t a_coloff = (uint32_t)((sel >> 1) * 8);
    uint32_t b_row    = (uint32_t)(wn * 32 + lr + (sel >> 1) * 8);
    uint32_t b_coloff = (uint32_t)((sel & 1) * 8);

    float C[2][4][4];
    #pragma unroll
    for (int t = 0; t < 2; t++)
        #pragma unroll
        for (int j = 0; j < 4; j++)
            #pragma unroll
            for (int q = 0; q < 4; q++) C[t][j][q] = 0.f;

    auto load_stage = [&](int kb, int s) {
        uint32_t sb = sb0 + s * MG_STG;
        int ko = kb * 64;
        #pragma unroll
        for (int i = 0; i < 16; i++) {
            const int tile = i >> 2;          // compile-time per unrolled i
            int u = tid + (i & 3) * 128;      // 0..511
            int r = u >> 3, c = u & 7;
            const bf16* src; uint32_t off; int rowb;
            if (tile == 0)      { src = Ah; off = MG_AH; rowb = bm; }
            else if (tile == 1) { src = Al; off = MG_AL; rowb = bm; }
            else if (tile == 2) { src = Bh; off = MG_BH; rowb = bn; }
            else                { src = Bl; off = MG_BL; rowb = bn; }
            cp_async16(sb + off + (uint32_t)(r * MG_PITCH + c * 16),
                       src + (size_t)(rowb + r) * K + ko + c * 8);
        }
        cp_commit();
    };

    load_stage(0, 0);

    for (int kb = 0; kb < KB; kb++) {
        if (kb + 1 < KB) {
            load_stage(kb + 1, (kb + 1) & 1);
            asm volatile("cp.async.wait_group 1;" ::: "memory");
        } else {
            asm volatile("cp.async.wait_group 0;" ::: "memory");
        }
        __syncthreads();

        uint32_t st = sb0 + (kb & 1) * MG_STG;
        #pragma unroll
        for (int step = 0; step < 4; step++) {
            int kbase = step * 16;
            uint32_t ah[2][4], al[2][4], bh[8], bl[8];
            #pragma unroll
            for (int t = 0; t < 2; t++) {
                uint32_t aa = st + MG_AH + (a_row + t * 16) * MG_PITCH + (kbase + a_coloff) * 2;
                ldmx4(ah[t], aa);
                ldmx4(al[t], aa + (MG_AL - MG_AH));
            }
            #pragma unroll
            for (int jp = 0; jp < 2; jp++) {
                uint32_t ba = st + MG_BH + (b_row + jp * 16) * MG_PITCH + (kbase + b_coloff) * 2;
                ldmx4(&bh[jp * 4], ba);
                ldmx4(&bl[jp * 4], ba + (MG_BL - MG_BH));
            }
            #pragma unroll
            for (int t = 0; t < 2; t++)
                #pragma unroll
                for (int j = 0; j < 4; j++) {
                    mma_bf16(C[t][j], ah[t], &bh[j * 2]);
                    mma_bf16(C[t][j], ah[t], &bl[j * 2]);
                    mma_bf16(C[t][j], al[t], &bh[j * 2]);
                }
        }
        __syncthreads();
    }

    bf16 *ph = o1h, *pl = o1l;
    int nstride = K3, coff = 0;
    if (MODE == 2 && bn >= K3) { ph = o2h; pl = o2l; nstride = DH; coff = K3; }
    #pragma unroll
    for (int t = 0; t < 2; t++) {
        int m0 = bm + wm * 32 + t * 16 + gid;
        #pragma unroll
        for (int j = 0; j < 4; j++) {
            int col = bn + wn * 32 + j * 8 + tid4 * 2;
            if (MODE == 2) {
                bf16 h0,l0,h1,l1;
                split_bf16(C[t][j][0], h0, l0); split_bf16(C[t][j][1], h1, l1);
                __nv_bfloat162 H = {h0,h1}, L = {l0,l1};
                *(uint32_t*)(ph + (size_t)m0 * nstride + col - coff) = *(uint32_t*)&H;
                *(uint32_t*)(pl + (size_t)m0 * nstride + col - coff) = *(uint32_t*)&L;
                split_bf16(C[t][j][2], h0, l0); split_bf16(C[t][j][3], h1, l1);
                __nv_bfloat162 H2 = {h0,h1}, L2 = {l0,l1};
                *(uint32_t*)(ph + (size_t)(m0 + 8) * nstride + col - coff) = *(uint32_t*)&H2;
                *(uint32_t*)(pl + (size_t)(m0 + 8) * nstride + col - coff) = *(uint32_t*)&L2;
            } else {
                *(float2*)(outf + (size_t)m0 * N + col)       = make_float2(C[t][j][0], C[t][j][1]);
                *(float2*)(outf + (size_t)(m0 + 8) * N + col) = make_float2(C[t][j][2], C[t][j][3]);
            }
        }
    }
}

// ---------------- fused pass 1: MLP-restructured dots + factored embeddings ----------------
__global__ void __launch_bounds__(512, 4) fused1_kernel(
    const float* __restrict__ HtC, const int* __restrict__ caps,
    const int* __restrict__ dists, const float* __restrict__ cemb,
    const float* __restrict__ demb, const float* __restrict__ qt,
    bf16* __restrict__ gbh, bf16* __restrict__ gbl)
{
    int b = blockIdx.x, tid = threadIdx.x;
    int w = tid >> 5, l = tid & 31;
    __shared__ __align__(16) float qs[DH];
    __shared__ int   cap_s[CC], dist_s[CC];
    __shared__ float cq_s[11], dq_s[3], wcap_s[11], wdist_s[3];
    __shared__ float logit_s[CC], attn_s[CC];

    qs[tid] = qt[(size_t)b * DH + tid];
    if (tid < CC) {
        cap_s[tid]  = caps[b * CC + tid];
        dist_s[tid] = dists[b * CC + tid];
    }
    __syncthreads();

    if (w < 14) {
        const float* trow = (w < 11) ? cemb + w * DH : demb + (w - 11) * DH;
        float a = 0.f;
        #pragma unroll
        for (int i = l; i < DH; i += 32) a += trow[i] * qs[i];
        #pragma unroll
        for (int o = 16; o; o >>= 1) a += __shfl_xor_sync(0xffffffffu, a, o);
        if (l == 0) { if (w < 11) cq_s[w] = a; else dq_s[w - 11] = a; }
    }

    const float4* H4 = (const float4*)HtC + (size_t)b * (CC * DH / 4);
    const float4* q4 = (const float4*)qs;
    float accr[4];
    #pragma unroll
    for (int r = 0; r < 4; r++) {
        const float4* hrow = H4 + (w * 4 + r) * 128;
        float acc = 0.f;
        #pragma unroll
        for (int j = 0; j < 4; j++) {
            int i = j * 32 + l;
            float4 h = hrow[i], q = q4[i];
            acc += h.x * q.x + h.y * q.y + h.z * q.z + h.w * q.w;
        }
        accr[r] = acc;
    }
    #pragma unroll
    for (int o = 16; o; o >>= 1) {
        accr[0] += __shfl_xor_sync(0xffffffffu, accr[0], o);
        accr[1] += __shfl_xor_sync(0xffffffffu, accr[1], o);
        accr[2] += __shfl_xor_sync(0xffffffffu, accr[2], o);
        accr[3] += __shfl_xor_sync(0xffffffffu, accr[3], o);
    }
    if (l == 0) {
        logit_s[w * 4 + 0] = accr[0];
        logit_s[w * 4 + 1] = accr[1];
        logit_s[w * 4 + 2] = accr[2];
        logit_s[w * 4 + 3] = accr[3];
    }
    __syncthreads();

    if (w == 0) {
        float x0 = (logit_s[l]      + cq_s[cap_s[l]]      + dq_s[dist_s[l]])      * SCALE;
        float x1 = (logit_s[l + 32] + cq_s[cap_s[l + 32]] + dq_s[dist_s[l + 32]]) * SCALE;
        float m = fmaxf(x0, x1);
        #pragma unroll
        for (int o = 16; o; o >>= 1) m = fmaxf(m, __shfl_xor_sync(0xffffffffu, m, o));
        float e0 = expf(x0 - m), e1 = expf(x1 - m);
        float s = e0 + e1;
        #pragma unroll
        for (int o = 16; o; o >>= 1) s += __shfl_xor_sync(0xffffffffu, s, o);
        float inv = 1.f / s;
        attn_s[l] = e0 * inv; attn_s[l + 32] = e1 * inv;
    }
    __syncthreads();

    if (tid < 11) {
        float s = 0.f;
        for (int c = 0; c < CC; c++) if (cap_s[c] == tid) s += attn_s[c];
        wcap_s[tid] = s;
    }
    if (tid >= 32 && tid < 35) {
        int u = tid - 32; float s = 0.f;
        for (int c = 0; c < CC; c++) if (dist_s[c] == u) s += attn_s[c];
        wdist_s[u] = s;
    }
    __syncthreads();

    const float* Hb = HtC + (size_t)b * (CC * DH);
    float a0 = 0.f, a1 = 0.f, a2 = 0.f, a3 = 0.f;
    #pragma unroll 4
    for (int c = 0; c < CC; c += 4) {
        a0 = fmaf(attn_s[c + 0], Hb[(c + 0) * DH + tid], a0);
        a1 = fmaf(attn_s[c + 1], Hb[(c + 1) * DH + tid], a1);
        a2 = fmaf(attn_s[c + 2], Hb[(c + 2) * DH + tid], a2);
        a3 = fmaf(attn_s[c + 3], Hb[(c + 3) * DH + tid], a3);
    }
    float acc = (a0 + a1) + (a2 + a3);
    #pragma unroll
    for (int v = 0; v < 11; v++)
        acc = fmaf(wcap_s[v], cemb[v * DH + tid], acc);
    #pragma unroll
    for (int u = 0; u < 3; u++)
        acc = fmaf(wdist_s[u], demb[u * DH + tid], acc);
    bf16 h, lo; split_bf16(acc, h, lo);
    gbh[(size_t)b * DH + tid] = h;
    gbl[(size_t)b * DH + tid] = lo;
}

// ---------------- fused pass 2: MLP-restructured streaming dots ----------------
__global__ void __launch_bounds__(512, 4) fused2_kernel(
    const float* __restrict__ HtC, const int* __restrict__ caps,
    const int* __restrict__ dists, const float* __restrict__ cemb,
    const float* __restrict__ demb, const float* __restrict__ kt,
    const void* __restrict__ dbl, float* __restrict__ out)
{
    int b = blockIdx.x, tid = threadIdx.x;
    int w = tid >> 5, l = tid & 31;
    __shared__ __align__(16) float ks[DH];
    __shared__ int   cap_s[CC], dist_s[CC];
    __shared__ float ck_s[11], dk_s[3];
    __shared__ float u_s[CC];

    ks[tid] = kt[(size_t)b * DH + tid];
    if (tid < CC) {
        cap_s[tid]  = caps[b * CC + tid];
        dist_s[tid] = dists[b * CC + tid];
    }
    __syncthreads();

    if (w < 14) {
        const float* trow = (w < 11) ? cemb + w * DH : demb + (w - 11) * DH;
        float a = 0.f;
        #pragma unroll
        for (int i = l; i < DH; i += 32) a += trow[i] * ks[i];
        #pragma unroll
        for (int o = 16; o; o >>= 1) a += __shfl_xor_sync(0xffffffffu, a, o);
        if (l == 0) { if (w < 11) ck_s[w] = a; else dk_s[w - 11] = a; }
    }

    const float4* H4 = (const float4*)HtC + (size_t)b * (CC * DH / 4);
    const float4* k4 = (const float4*)ks;
    float accr[4];
    #pragma unroll
    for (int r = 0; r < 4; r++) {
        const float4* hrow = H4 + (w * 4 + r) * 128;
        float acc = 0.f;
        #pragma unroll
        for (int j = 0; j < 4; j++) {
            int i = j * 32 + l;
            float4 h = __ldcs(hrow + i);
            float4 q = k4[i];
            acc += h.x * q.x + h.y * q.y + h.z * q.z + h.w * q.w;
        }
        accr[r] = acc;
    }
    #pragma unroll
    for (int o = 16; o; o >>= 1) {
        accr[0] += __shfl_xor_sync(0xffffffffu, accr[0], o);
        accr[1] += __shfl_xor_sync(0xffffffffu, accr[1], o);
        accr[2] += __shfl_xor_sync(0xffffffffu, accr[2], o);
        accr[3] += __shfl_xor_sync(0xffffffffu, accr[3], o);
    }
    if (l == 0) {
        u_s[w * 4 + 0] = accr[0];
        u_s[w * 4 + 1] = accr[1];
        u_s[w * 4 + 2] = accr[2];
        u_s[w * 4 + 3] = accr[3];
    }
    __syncthreads();

    if (w == 0) {
        int dval = g_dbl_is_u8 ? (int)((const unsigned char*)dbl)[b]
                               : ((const int*)dbl)[b];
        int need = dval ? 2 : 1;
        float x0 = (u_s[l]      + ck_s[cap_s[l]]      + dk_s[dist_s[l]])      * SCALE;
        float x1 = (u_s[l + 32] + ck_s[cap_s[l + 32]] + dk_s[dist_s[l + 32]]) * SCALE;
        if (cap_s[l]      < need) x0 = __int_as_float(0xff800000);
        if (cap_s[l + 32] < need) x1 = __int_as_float(0xff800000);
        float m = fmaxf(x0, x1);
        #pragma unroll
        for (int o = 16; o; o >>= 1) m = fmaxf(m, __shfl_xor_sync(0xffffffffu, m, o));
        float e0 = expf(x0 - m), e1 = expf(x1 - m);
        float s = e0 + e1;
        #pragma unroll
        for (int o = 16; o; o >>= 1) s += __shfl_xor_sync(0xffffffffu, s, o);
        float inv = 1.f / s;
        out[(size_t)b * CC + l]      = e0 * inv;
        out[(size_t)b * CC + l + 32] = e1 * inv;
    }
}

extern "C" void kernel_launch(void* const* d_in, const int* in_sizes, int n_in,
                              void* d_out, int out_size) {
    const float* HtC   = (const float*)d_in[0];
    const int*   caps  = (const int*)  d_in[1];
    const int*   dists = (const int*)  d_in[2];
    const float* HX    = (const float*)d_in[3];
    const float* HS    = (const float*)d_in[4];
    const float* EQ    = (const float*)d_in[5];
    const void*  dbl   = d_in[6];
    const float* cemb  = (const float*)d_in[7];
    const float* demb  = (const float*)d_in[8];
    const float* Wq    = (const float*)d_in[9];
    const float* Wk    = (const float*)d_in[10];
    const float* Wv    = (const float*)d_in[11];
    float* out = (float*)d_out;

    bf16 *ctxh,*ctxl,*wbh,*wbl,*wkh,*wkl,*w1h,*w1l,*m2h,*m2l,*gbh,*gbl;
    float *qt,*kt;
    cudaGetSymbolAddress((void**)&ctxh, g_ctx_h);  cudaGetSymbolAddress((void**)&ctxl, g_ctx_l);
    cudaGetSymbolAddress((void**)&wbh,  g_WBT_h);  cudaGetSymbolAddress((void**)&wbl,  g_WBT_l);
    cudaGetSymbolAddress((void**)&wkh,  g_WkT_h);  cudaGetSymbolAddress((void**)&wkl,  g_WkT_l);
    cudaGetSymbolAddress((void**)&w1h,  g_W1t_h);  cudaGetSymbolAddress((void**)&w1l,  g_W1t_l);
    cudaGetSymbolAddress((void**)&m2h,  g_M2t_h);  cudaGetSymbolAddress((void**)&m2l,  g_M2t_l);
    cudaGetSymbolAddress((void**)&gbh,  g_gbar_h); cudaGetSymbolAddress((void**)&gbl,  g_gbar_l);
    cudaGetSymbolAddress((void**)&qt,   g_qt);     cudaGetSymbolAddress((void**)&kt,   g_kt);

    cudaFuncSetAttribute(mma_gemm_kernel<0>, cudaFuncAttributeMaxDynamicSharedMemorySize, MG_SMEM);
    cudaFuncSetAttribute(mma_gemm_kernel<2>, cudaFuncAttributeMaxDynamicSharedMemorySize, MG_SMEM);

    // 1) prep: weight transposes (B concat) + context pack/split + dtype sniff
    prep_kernel<<<4353, 256>>>(Wq, Wk, Wv, wbh, wbl, wkh, wkl,
                               (uint2*)ctxh, (uint2*)ctxl,
                               (const float4*)HX, (const float4*)HS, (const float4*)EQ,
                               (const unsigned char*)dbl);
    // 2) fold (merged): D[d, 0..2047] = sum_e WkT[d,e]*WBT[n,e] -> W1t | M2t
    mma_gemm_kernel<2><<<dim3(NB2/64, DH/64), 128, MG_SMEM>>>(
        nullptr, w1h, w1l, m2h, m2l, wkh, wkl, wbh, wbl, NB2, DH);
    // 3) qt[b,d] = sum_i ctx[b,i]*W1t[d,i]    (M=2048, N=512, K=1536)
    mma_gemm_kernel<0><<<dim3(DH/64, BB/64), 128, MG_SMEM>>>(
        qt, nullptr, nullptr, nullptr, nullptr, ctxh, ctxl, w1h, w1l, DH, K3);
    // 4) logits/softmax/gbar
    fused1_kernel<<<BB, 512>>>(HtC, caps, dists, cemb, demb, qt, gbh, gbl);
    // 5) kt[b,d] = sum_e2 gbar[b,e2]*M2t[d,e2] (M=2048, N=512, K=512)
    mma_gemm_kernel<0><<<dim3(DH/64, BB/64), 128, MG_SMEM>>>(
        kt, nullptr, nullptr, nullptr, nullptr, gbh, gbl, m2h, m2l, DH, DH);
    // 6) u/mask/softmax -> out
    fused2_kernel<<<BB, 512>>>(HtC, caps, dists, cemb, demb, kt, dbl, out);
}

// round 16
// speedup vs baseline: 1.1275x; 1.0032x over previous
#include <cuda_runtime.h>
#include <cuda_bf16.h>
#include <math.h>
#include <stdint.h>

// Problem constants
#define BB   2048
#define CC   64
#define DH   512
#define K3   1536
#define NB2  (K3 + DH)                 // concat fold-B rows
#define SCALE 0.044194173824159216f   // 1/sqrt(512)

typedef unsigned long long u64;
typedef __nv_bfloat16 bf16;

// ---------------- scratch (static device globals) ----------------
__device__ bf16  g_ctx_h [BB * K3];
__device__ bf16  g_ctx_l [BB * K3];
__device__ bf16  g_WBT_h [NB2 * DH];  // rows 0..1535: WqT[i,e]; rows 1536..2047: WvT[e2,e]
__device__ bf16  g_WBT_l [NB2 * DH];
__device__ bf16  g_WkT_h [DH * DH];
__device__ bf16  g_WkT_l [DH * DH];
__device__ bf16  g_W1t_h [DH * K3];   // W1t[d,i] = sum_e WkT[d,e]*WqT[i,e]
__device__ bf16  g_W1t_l [DH * K3];
__device__ bf16  g_M2t_h [DH * DH];   // M2t[d,e2] = sum_e WkT[d,e]*WvT[e2,e]
__device__ bf16  g_M2t_l [DH * DH];
__device__ float g_qt    [BB * DH];
__device__ bf16  g_gbar_h[BB * DH];
__device__ bf16  g_gbar_l[BB * DH];
__device__ float g_kt    [BB * DH];
__device__ int   g_dbl_is_u8;

// ---------------- helpers ----------------
__device__ __forceinline__ uint32_t smem_u32(const void* p) {
    uint32_t a;
    asm("{ .reg .u64 t; cvta.to.shared.u64 t, %1; cvt.u32.u64 %0, t; }" : "=r"(a) : "l"(p));
    return a;
}
__device__ __forceinline__ void cp_async16(uint32_t dst, const void* src) {
    asm volatile("cp.async.cg.shared.global [%0], [%1], 16;" :: "r"(dst), "l"(src) : "memory");
}
__device__ __forceinline__ void cp_commit() {
    asm volatile("cp.async.commit_group;" ::: "memory");
}
__device__ __forceinline__ void split_bf16(float f, bf16& h, bf16& l) {
    h = __float2bfloat16_rn(f);
    l = __float2bfloat16_rn(f - __bfloat162float(h));
}
__device__ __forceinline__ void mma_bf16(float* c, const uint32_t* a, const uint32_t* b) {
    asm volatile(
        "mma.sync.aligned.m16n8k16.row.col.f32.bf16.bf16.f32 "
        "{%0,%1,%2,%3}, {%4,%5,%6,%7}, {%8,%9}, {%0,%1,%2,%3};"
        : "+f"(c[0]), "+f"(c[1]), "+f"(c[2]), "+f"(c[3])
        : "r"(a[0]), "r"(a[1]), "r"(a[2]), "r"(a[3]), "r"(b[0]), "r"(b[1]));
}
__device__ __forceinline__ void ldmx4(uint32_t* r, uint32_t saddr) {
    asm volatile("ldmatrix.sync.aligned.m8n8.x4.shared.b16 {%0,%1,%2,%3}, [%4];"
        : "=r"(r[0]), "=r"(r[1]), "=r"(r[2]), "=r"(r[3]) : "r"(saddr));
}

// ---------------- prep: transposes+splits, context pack, dtype sniff ----------------
__global__ void prep_kernel(const float* __restrict__ Wq,
                            const float* __restrict__ Wk,
                            const float* __restrict__ Wv,
                            bf16* __restrict__ wbh, bf16* __restrict__ wbl,
                            bf16* __restrict__ wkh, bf16* __restrict__ wkl,
                            uint2* __restrict__ ch, uint2* __restrict__ cl,
                            const float4* __restrict__ hx,
                            const float4* __restrict__ hs,
                            const float4* __restrict__ eq,
                            const unsigned char* __restrict__ dblp) {
    int bid = blockIdx.x;
    if (bid == 1280) {
        __shared__ int any;
        if (threadIdx.x == 0) any = 0;
        __syncthreads();
        int found = 0;
        for (int i = threadIdx.x; i < 2048; i += 256)
            if ((i & 3) && dblp[i]) found = 1;
        if (found) any = 1;
        __syncthreads();
        if (threadIdx.x == 0) g_dbl_is_u8 = any;
        return;
    }
    if (bid > 1280) {
        int idx = (bid - 1281) * 256 + threadIdx.x;   // BB*384 float4s
        int b = idx / 384;
        int r = idx - b * 384;
        float4 v;
        if (r < 128)       v = hx[b * 128 + r];
        else if (r < 256)  v = hs[b * 128 + (r - 128)];
        else               v = eq[b * 128 + (r - 256)];
        bf16 h0,l0,h1,l1,h2,l2,h3,l3;
        split_bf16(v.x,h0,l0); split_bf16(v.y,h1,l1);
        split_bf16(v.z,h2,l2); split_bf16(v.w,h3,l3);
        __nv_bfloat162 H01 = {h0,h1}, H23 = {h2,h3}, L01 = {l0,l1}, L23 = {l2,l3};
        ch[idx] = make_uint2(*(uint32_t*)&H01, *(uint32_t*)&H23);
        cl[idx] = make_uint2(*(uint32_t*)&L01, *(uint32_t*)&L23);
        return;
    }
    int tx = threadIdx.x & 31, ty = threadIdx.x >> 5;   // 32 x 8
    const float* in; bf16 *oh, *ol; int Cn, bx, by, roff;
    if (bid < 768)       { in = Wq; oh = wbh; ol = wbl; Cn = K3; bx = bid % 48;          by = bid / 48;         roff = 0; }
    else if (bid < 1024) { in = Wk; oh = wkh; ol = wkl; Cn = DH; bx = (bid - 768) & 15;  by = (bid - 768) >> 4; roff = 0; }
    else                 { in = Wv; oh = wbh; ol = wbl; Cn = DH; bx = (bid - 1024) & 15; by = (bid - 1024) >> 4; roff = K3; }
    __shared__ float t[32][33];
    int i0 = bx * 32, e0 = by * 32;
    #pragma unroll
    for (int j = 0; j < 32; j += 8)
        t[ty + j][tx] = in[(size_t)(e0 + ty + j) * Cn + i0 + tx];
    __syncthreads();
    #pragma unroll
    for (int j = 0; j < 32; j += 8) {
        float f = t[tx][ty + j];
        bf16 h, l; split_bf16(f, h, l);
        size_t o = (size_t)(roff + i0 + ty + j) * DH + e0 + tx;
        oh[o] = h; ol[o] = l;
    }
}

// ---------------- mma.sync GEMM: BK=64, 2-stage ----------------
#define MG_PITCH 144
#define MG_AH   0
#define MG_AL   9216
#define MG_BH   18432
#define MG_BL   27648
#define MG_STG  36864
#define MG_SMEM (2 * MG_STG)

template<int MODE>
__global__ void __launch_bounds__(128, 2) mma_gemm_kernel(
    float* __restrict__ outf,
    bf16* __restrict__ o1h, bf16* __restrict__ o1l,
    bf16* __restrict__ o2h, bf16* __restrict__ o2l,
    const bf16* __restrict__ Ah, const bf16* __restrict__ Al,
    const bf16* __restrict__ Bh, const bf16* __restrict__ Bl,
    int N, int K)
{
    extern __shared__ char dsm[];
    uint32_t sb0 = smem_u32(dsm);

    int tid = threadIdx.x;
    int lane = tid & 31, wid = tid >> 5;
    int wm = wid & 1, wn = wid >> 1;
    int gid = lane >> 2, tid4 = lane & 3;
    int lr = lane & 7, sel = lane >> 3;
    int bm = blockIdx.y * 64, bn = blockIdx.x * 64;
    int KB = K >> 6;

    uint32_t a_row    = (uint32_t)(wm * 32 + lr + (sel & 1) * 8);
    uint32_t a_coloff = (uint32_t)((sel >> 1) * 8);
    uint32_t b_row    = (uint32_t)(wn * 32 + lr + (sel >> 1) * 8);
    uint32_t b_coloff = (uint32_t)((sel & 1) * 8);

    float C[2][4][4];
    #pragma unroll
    for (int t = 0; t < 2; t++)
        #pragma unroll
        for (int j = 0; j < 4; j++)
            #pragma unroll
            for (int q = 0; q < 4; q++) C[t][j][q] = 0.f;

    auto load_stage = [&](int kb, int s) {
        uint32_t sb = sb0 + s * MG_STG;
        int ko = kb * 64;
        #pragma unroll
        for (int i = 0; i < 16; i++) {
            const int tile = i >> 2;
            int u = tid + (i & 3) * 128;
            int r = u >> 3, c = u & 7;
            const bf16* src; uint32_t off; int rowb;
            if (tile == 0)      { src = Ah; off = MG_AH; rowb = bm; }
            else if (tile == 1) { src = Al; off = MG_AL; rowb = bm; }
            else if (tile == 2) { src = Bh; off = MG_BH; rowb = bn; }
            else                { src = Bl; off = MG_BL; rowb = bn; }
            cp_async16(sb + off + (uint32_t)(r * MG_PITCH + c * 16),
                       src + (size_t)(rowb + r) * K + ko + c * 8);
        }
        cp_commit();
    };

    load_stage(0, 0);

    for (int kb = 0; kb < KB; kb++) {
        if (kb + 1 < KB) {
            load_stage(kb + 1, (kb + 1) & 1);
            asm volatile("cp.async.wait_group 1;" ::: "memory");
        } else {
            asm volatile("cp.async.wait_group 0;" ::: "memory");
        }
        __syncthreads();

        uint32_t st = sb0 + (kb & 1) * MG_STG;
        #pragma unroll
        for (int step = 0; step < 4; step++) {
            int kbase = step * 16;
            uint32_t ah[2][4], al[2][4], bh[8], bl[8];
            #pragma unroll
            for (int t = 0; t < 2; t++) {
                uint32_t aa = st + MG_AH + (a_row + t * 16) * MG_PITCH + (kbase + a_coloff) * 2;
                ldmx4(ah[t], aa);
                ldmx4(al[t], aa + (MG_AL - MG_AH));
            }
            #pragma unroll
            for (int jp = 0; jp < 2; jp++) {
                uint32_t ba = st + MG_BH + (b_row + jp * 16) * MG_PITCH + (kbase + b_coloff) * 2;
                ldmx4(&bh[jp * 4], ba);
                ldmx4(&bl[jp * 4], ba + (MG_BL - MG_BH));
            }
            #pragma unroll
            for (int t = 0; t < 2; t++)
                #pragma unroll
                for (int j = 0; j < 4; j++) {
                    mma_bf16(C[t][j], ah[t], &bh[j * 2]);
                    mma_bf16(C[t][j], ah[t], &bl[j * 2]);
                    mma_bf16(C[t][j], al[t], &bh[j * 2]);
                }
        }
        __syncthreads();
    }

    bf16 *ph = o1h, *pl = o1l;
    int nstride = K3, coff = 0;
    if (MODE == 2 && bn >= K3) { ph = o2h; pl = o2l; nstride = DH; coff = K3; }
    #pragma unroll
    for (int t = 0; t < 2; t++) {
        int m0 = bm + wm * 32 + t * 16 + gid;
        #pragma unroll
        for (int j = 0; j < 4; j++) {
            int col = bn + wn * 32 + j * 8 + tid4 * 2;
            if (MODE == 2) {
                bf16 h0,l0,h1,l1;
                split_bf16(C[t][j][0], h0, l0); split_bf16(C[t][j][1], h1, l1);
                __nv_bfloat162 H = {h0,h1}, L = {l0,l1};
                *(uint32_t*)(ph + (size_t)m0 * nstride + col - coff) = *(uint32_t*)&H;
                *(uint32_t*)(pl + (size_t)m0 * nstride + col - coff) = *(uint32_t*)&L;
                split_bf16(C[t][j][2], h0, l0); split_bf16(C[t][j][3], h1, l1);
                __nv_bfloat162 H2 = {h0,h1}, L2 = {l0,l1};
                *(uint32_t*)(ph + (size_t)(m0 + 8) * nstride + col - coff) = *(uint32_t*)&H2;
                *(uint32_t*)(pl + (size_t)(m0 + 8) * nstride + col - coff) = *(uint32_t*)&L2;
            } else {
                *(float2*)(outf + (size_t)m0 * N + col)       = make_float2(C[t][j][0], C[t][j][1]);
                *(float2*)(outf + (size_t)(m0 + 8) * N + col) = make_float2(C[t][j][2], C[t][j][3]);
            }
        }
    }
}

// ---------------- fused pass 1: vectorized gbar + factored embeddings ----------------
__global__ void __launch_bounds__(512, 4) fused1_kernel(
    const float* __restrict__ HtC, const int* __restrict__ caps,
    const int* __restrict__ dists, const float* __restrict__ cemb,
    const float* __restrict__ demb, const float* __restrict__ qt,
    bf16* __restrict__ gbh, bf16* __restrict__ gbl)
{
    int b = blockIdx.x, tid = threadIdx.x;
    int w = tid >> 5, l = tid & 31;
    __shared__ __align__(16) float qs[DH];
    __shared__ __align__(16) float pr[4][DH];   // gbar partials (8 KB)
    __shared__ int   cap_s[CC], dist_s[CC];
    __shared__ float cq_s[11], dq_s[3], wcap_s[11], wdist_s[3];
    __shared__ float logit_s[CC], attn_s[CC];

    qs[tid] = qt[(size_t)b * DH + tid];
    if (tid < CC) {
        cap_s[tid]  = caps[b * CC + tid];
        dist_s[tid] = dists[b * CC + tid];
    }
    __syncthreads();

    // table dots: warps 0..10 -> cq, 11..13 -> dq
    if (w < 14) {
        const float* trow = (w < 11) ? cemb + w * DH : demb + (w - 11) * DH;
        float a = 0.f;
        #pragma unroll
        for (int i = l; i < DH; i += 32) a += trow[i] * qs[i];
        #pragma unroll
        for (int o = 16; o; o >>= 1) a += __shfl_xor_sync(0xffffffffu, a, o);
        if (l == 0) { if (w < 11) cq_s[w] = a; else dq_s[w - 11] = a; }
    }

    // row dots: 4 independent accumulators, batched loads, interleaved reductions
    const float4* H4 = (const float4*)HtC + (size_t)b * (CC * DH / 4);
    const float4* q4 = (const float4*)qs;
    float accr[4];
    #pragma unroll
    for (int r = 0; r < 4; r++) {
        const float4* hrow = H4 + (w * 4 + r) * 128;
        float acc = 0.f;
        #pragma unroll
        for (int j = 0; j < 4; j++) {
            int i = j * 32 + l;
            float4 h = hrow[i], q = q4[i];
            acc += h.x * q.x + h.y * q.y + h.z * q.z + h.w * q.w;
        }
        accr[r] = acc;
    }
    #pragma unroll
    for (int o = 16; o; o >>= 1) {
        accr[0] += __shfl_xor_sync(0xffffffffu, accr[0], o);
        accr[1] += __shfl_xor_sync(0xffffffffu, accr[1], o);
        accr[2] += __shfl_xor_sync(0xffffffffu, accr[2], o);
        accr[3] += __shfl_xor_sync(0xffffffffu, accr[3], o);
    }
    if (l == 0) {
        logit_s[w * 4 + 0] = accr[0];
        logit_s[w * 4 + 1] = accr[1];
        logit_s[w * 4 + 2] = accr[2];
        logit_s[w * 4 + 3] = accr[3];
    }
    __syncthreads();

    if (w == 0) {
        float x0 = (logit_s[l]      + cq_s[cap_s[l]]      + dq_s[dist_s[l]])      * SCALE;
        float x1 = (logit_s[l + 32] + cq_s[cap_s[l + 32]] + dq_s[dist_s[l + 32]]) * SCALE;
        float m = fmaxf(x0, x1);
        #pragma unroll
        for (int o = 16; o; o >>= 1) m = fmaxf(m, __shfl_xor_sync(0xffffffffu, m, o));
        float e0 = expf(x0 - m), e1 = expf(x1 - m);
        float s = e0 + e1;
        #pragma unroll
        for (int o = 16; o; o >>= 1) s += __shfl_xor_sync(0xffffffffu, s, o);
        float inv = 1.f / s;
        attn_s[l] = e0 * inv; attn_s[l + 32] = e1 * inv;
    }
    __syncthreads();

    // index-grouped attn weights
    if (tid < 11) {
        float s = 0.f;
        for (int c = 0; c < CC; c++) if (cap_s[c] == tid) s += attn_s[c];
        wcap_s[tid] = s;
    }
    if (tid >= 32 && tid < 35) {
        int u = tid - 32; float s = 0.f;
        for (int c = 0; c < CC; c++) if (dist_s[c] == u) s += attn_s[c];
        wdist_s[u] = s;
    }

    // gbar partials: thread t -> c-group g = t>>7 (16 rows), d-quad dq = t&127
    // float4 loads (4x fewer wavefronts than scalar), two acc4 chains.
    {
        int g = tid >> 7, dq = tid & 127;
        const float4* Hb4 = H4;   // same base
        float4 e0 = make_float4(0.f, 0.f, 0.f, 0.f);
        float4 e1 = make_float4(0.f, 0.f, 0.f, 0.f);
        #pragma unroll
        for (int i = 0; i < 16; i += 2) {
            int c0 = g * 16 + i;
            float4 h0 = Hb4[(c0 + 0) * 128 + dq];
            float4 h1 = Hb4[(c0 + 1) * 128 + dq];
            float a0 = attn_s[c0 + 0], a1 = attn_s[c0 + 1];
            e0.x = fmaf(a0, h0.x, e0.x); e0.y = fmaf(a0, h0.y, e0.y);
            e0.z = fmaf(a0, h0.z, e0.z); e0.w = fmaf(a0, h0.w, e0.w);
            e1.x = fmaf(a1, h1.x, e1.x); e1.y = fmaf(a1, h1.y, e1.y);
            e1.z = fmaf(a1, h1.z, e1.z); e1.w = fmaf(a1, h1.w, e1.w);
        }
        float4 tot = make_float4(e0.x + e1.x, e0.y + e1.y, e0.z + e1.z, e0.w + e1.w);
        *(float4*)&pr[g][dq * 4] = tot;
    }
    __syncthreads();

    // final: reduce 4 groups, add factored embedding terms, split-store
    float acc = (pr[0][tid] + pr[1][tid]) + (pr[2][tid] + pr[3][tid]);
    #pragma unroll
    for (int v = 0; v < 11; v++)
        acc = fmaf(wcap_s[v], cemb[v * DH + tid], acc);
    #pragma unroll
    for (int u = 0; u < 3; u++)
        acc = fmaf(wdist_s[u], demb[u * DH + tid], acc);
    bf16 h, lo; split_bf16(acc, h, lo);
    gbh[(size_t)b * DH + tid] = h;
    gbl[(size_t)b * DH + tid] = lo;
}

// ---------------- fused pass 2: MLP-restructured streaming dots ----------------
__global__ void __launch_bounds__(512, 4) fused2_kernel(
    const float* __restrict__ HtC, const int* __restrict__ caps,
    const int* __restrict__ dists, const float* __restrict__ cemb,
    const float* __restrict__ demb, const float* __restrict__ kt,
    const void* __restrict__ dbl, float* __restrict__ out)
{
    int b = blockIdx.x, tid = threadIdx.x;
    int w = tid >> 5, l = tid & 31;
    __shared__ __align__(16) float ks[DH];
    __shared__ int   cap_s[CC], dist_s[CC];
    __shared__ float ck_s[11], dk_s[3];
    __shared__ float u_s[CC];

    ks[tid] = kt[(size_t)b * DH + tid];
    if (tid < CC) {
        cap_s[tid]  = caps[b * CC + tid];
        dist_s[tid] = dists[b * CC + tid];
    }
    __syncthreads();

    if (w < 14) {
        const float* trow = (w < 11) ? cemb + w * DH : demb + (w - 11) * DH;
        float a = 0.f;
        #pragma unroll
        for (int i = l; i < DH; i += 32) a += trow[i] * ks[i];
        #pragma unroll
        for (int o = 16; o; o >>= 1) a += __shfl_xor_sync(0xffffffffu, a, o);
        if (l == 0) { if (w < 11) ck_s[w] = a; else dk_s[w - 11] = a; }
    }

    const float4* H4 = (const float4*)HtC + (size_t)b * (CC * DH / 4);
    const float4* k4 = (const float4*)ks;
    float accr[4];
    #pragma unroll
    for (int r = 0; r < 4; r++) {
        const float4* hrow = H4 + (w * 4 + r) * 128;
        float acc = 0.f;
        #pragma unroll
        for (int j = 0; j < 4; j++) {
            int i = j * 32 + l;
            float4 h = __ldcs(hrow + i);
            float4 q = k4[i];
            acc += h.x * q.x + h.y * q.y + h.z * q.z + h.w * q.w;
        }
        accr[r] = acc;
    }
    #pragma unroll
    for (int o = 16; o; o >>= 1) {
        accr[0] += __shfl_xor_sync(0xffffffffu, accr[0], o);
        accr[1] += __shfl_xor_sync(0xffffffffu, accr[1], o);
        accr[2] += __shfl_xor_sync(0xffffffffu, accr[2], o);
        accr[3] += __shfl_xor_sync(0xffffffffu, accr[3], o);
    }
    if (l == 0) {
        u_s[w * 4 + 0] = accr[0];
        u_s[w * 4 + 1] = accr[1];
        u_s[w * 4 + 2] = accr[2];
        u_s[w * 4 + 3] = accr[3];
    }
    __syncthreads();

    if (w == 0) {
        int dval = g_dbl_is_u8 ? (int)((const unsigned char*)dbl)[b]
                               : ((const int*)dbl)[b];
        int need = dval ? 2 : 1;
        float x0 = (u_s[l]      + ck_s[cap_s[l]]      + dk_s[dist_s[l]])      * SCALE;
        float x1 = (u_s[l + 32] + ck_s[cap_s[l + 32]] + dk_s[dist_s[l + 32]]) * SCALE;
        if (cap_s[l]      < need) x0 = __int_as_float(0xff800000);
        if (cap_s[l + 32] < need) x1 = __int_as_float(0xff800000);
        float m = fmaxf(x0, x1);
        #pragma unroll
        for (int o = 16; o; o >>= 1) m = fmaxf(m, __shfl_xor_sync(0xffffffffu, m, o));
        float e0 = expf(x0 - m), e1 = expf(x1 - m);
        float s = e0 + e1;
        #pragma unroll
        for (int o = 16; o; o >>= 1) s += __shfl_xor_sync(0xffffffffu, s, o);
        float inv = 1.f / s;
        out[(size_t)b * CC + l]      = e0 * inv;
        out[(size_t)b * CC + l + 32] = e1 * inv;
    }
}

extern "C" void kernel_launch(void* const* d_in, const int* in_sizes, int n_in,
                              void* d_out, int out_size) {
    const float* HtC   = (const float*)d_in[0];
    const int*   caps  = (const int*)  d_in[1];
    const int*   dists = (const int*)  d_in[2];
    const float* HX    = (const float*)d_in[3];
    const float* HS    = (const float*)d_in[4];
    const float* EQ    = (const float*)d_in[5];
    const void*  dbl   = d_in[6];
    const float* cemb  = (const float*)d_in[7];
    const float* demb  = (const float*)d_in[8];
    const float* Wq    = (const float*)d_in[9];
    const float* Wk    = (const float*)d_in[10];
    const float* Wv    = (const float*)d_in[11];
    float* out = (float*)d_out;

    bf16 *ctxh,*ctxl,*wbh,*wbl,*wkh,*wkl,*w1h,*w1l,*m2h,*m2l,*gbh,*gbl;
    float *qt,*kt;
    cudaGetSymbolAddress((void**)&ctxh, g_ctx_h);  cudaGetSymbolAddress((void**)&ctxl, g_ctx_l);
    cudaGetSymbolAddress((void**)&wbh,  g_WBT_h);  cudaGetSymbolAddress((void**)&wbl,  g_WBT_l);
    cudaGetSymbolAddress((void**)&wkh,  g_WkT_h);  cudaGetSymbolAddress((void**)&wkl,  g_WkT_l);
    cudaGetSymbolAddress((void**)&w1h,  g_W1t_h);  cudaGetSymbolAddress((void**)&w1l,  g_W1t_l);
    cudaGetSymbolAddress((void**)&m2h,  g_M2t_h);  cudaGetSymbolAddress((void**)&m2l,  g_M2t_l);
    cudaGetSymbolAddress((void**)&gbh,  g_gbar_h); cudaGetSymbolAddress((void**)&gbl,  g_gbar_l);
    cudaGetSymbolAddress((void**)&qt,   g_qt);     cudaGetSymbolAddress((void**)&kt,   g_kt);

    cudaFuncSetAttribute(mma_gemm_kernel<0>, cudaFuncAttributeMaxDynamicSharedMemorySize, MG_SMEM);
    cudaFuncSetAttribute(mma_gemm_kernel<2>, cudaFuncAttributeMaxDynamicSharedMemorySize, MG_SMEM);

    // 1) prep: weight transposes (B concat) + context pack/split + dtype sniff
    prep_kernel<<<4353, 256>>>(Wq, Wk, Wv, wbh, wbl, wkh, wkl,
                               (uint2*)ctxh, (uint2*)ctxl,
                               (const float4*)HX, (const float4*)HS, (const float4*)EQ,
                               (const unsigned char*)dbl);
    // 2) fold (merged): D[d, 0..2047] = sum_e WkT[d,e]*WBT[n,e] -> W1t | M2t
    mma_gemm_kernel<2><<<dim3(NB2/64, DH/64), 128, MG_SMEM>>>(
        nullptr, w1h, w1l, m2h, m2l, wkh, wkl, wbh, wbl, NB2, DH);
    // 3) qt[b,d] = sum_i ctx[b,i]*W1t[d,i]    (M=2048, N=512, K=1536)
    mma_gemm_kernel<0><<<dim3(DH/64, BB/64), 128, MG_SMEM>>>(
        qt, nullptr, nullptr, nullptr, nullptr, ctxh, ctxl, w1h, w1l, DH, K3);
    // 4) logits/softmax/gbar (vectorized gbar)
    fused1_kernel<<<BB, 512>>>(HtC, caps, dists, cemb, demb, qt, gbh, gbl);
    // 5) kt[b,d] = sum_e2 gbar[b,e2]*M2t[d,e2] (M=2048, N=512, K=512)
    mma_gemm_kernel<0><<<dim3(DH/64, BB/64), 128, MG_SMEM>>>(
        kt, nullptr, nullptr, nullptr, nullptr, gbh, gbl, m2h, m2l, DH, DH);
    // 6) u/mask/softmax -> out
    fused2_kernel<<<BB, 512>>>(HtC, caps, dists, cemb, demb, kt, dbl, out);
}

// round 17
// speedup vs baseline: 1.1499x; 1.0199x over previous
#include <cuda_runtime.h>
#include <cuda_bf16.h>
#include <math.h>
#include <stdint.h>

// Problem constants
#define BB   2048
#define CC   64
#define DH   512
#define K3   1536
#define NB2  (K3 + DH)                 // concat fold-B rows
#define SCALE 0.044194173824159216f   // 1/sqrt(512)

typedef unsigned long long u64;
typedef __nv_bfloat16 bf16;

// ---------------- scratch (static device globals) ----------------
__device__ bf16  g_ctx_h [BB * K3];
__device__ bf16  g_ctx_l [BB * K3];
__device__ bf16  g_WBT_h [NB2 * DH];
__device__ bf16  g_WBT_l [NB2 * DH];
__device__ bf16  g_WkT_h [DH * DH];
__device__ bf16  g_WkT_l [DH * DH];
__device__ bf16  g_W1t_h [DH * K3];
__device__ bf16  g_W1t_l [DH * K3];
__device__ bf16  g_M2t_h [DH * DH];
__device__ bf16  g_M2t_l [DH * DH];
__device__ float g_qt    [BB * DH];
__device__ bf16  g_gbar_h[BB * DH];
__device__ bf16  g_gbar_l[BB * DH];
__device__ float g_kt    [BB * DH];
__device__ int   g_dbl_is_u8;
__device__ uint32_t g_pf_sink[64];    // prefetch XOR sink (keeps loads alive)

// ---------------- helpers ----------------
__device__ __forceinline__ uint32_t smem_u32(const void* p) {
    uint32_t a;
    asm("{ .reg .u64 t; cvta.to.shared.u64 t, %1; cvt.u32.u64 %0, t; }" : "=r"(a) : "l"(p));
    return a;
}
__device__ __forceinline__ void cp_async16(uint32_t dst, const void* src) {
    asm volatile("cp.async.cg.shared.global [%0], [%1], 16;" :: "r"(dst), "l"(src) : "memory");
}
__device__ __forceinline__ void cp_commit() {
    asm volatile("cp.async.commit_group;" ::: "memory");
}
__device__ __forceinline__ void split_bf16(float f, bf16& h, bf16& l) {
    h = __float2bfloat16_rn(f);
    l = __float2bfloat16_rn(f - __bfloat162float(h));
}
__device__ __forceinline__ void mma_bf16(float* c, const uint32_t* a, const uint32_t* b) {
    asm volatile(
        "mma.sync.aligned.m16n8k16.row.col.f32.bf16.bf16.f32 "
        "{%0,%1,%2,%3}, {%4,%5,%6,%7}, {%8,%9}, {%0,%1,%2,%3};"
        : "+f"(c[0]), "+f"(c[1]), "+f"(c[2]), "+f"(c[3])
        : "r"(a[0]), "r"(a[1]), "r"(a[2]), "r"(a[3]), "r"(b[0]), "r"(b[1]));
}
__device__ __forceinline__ void ldmx4(uint32_t* r, uint32_t saddr) {
    asm volatile("ldmatrix.sync.aligned.m8n8.x4.shared.b16 {%0,%1,%2,%3}, [%4];"
        : "=r"(r[0]), "=r"(r[1]), "=r"(r[2]), "=r"(r[3]) : "r"(saddr));
}

// ---------------- prep: transposes+splits, context pack, dtype sniff ----------------
__global__ void prep_kernel(const float* __restrict__ Wq,
                            const float* __restrict__ Wk,
                            const float* __restrict__ Wv,
                            bf16* __restrict__ wbh, bf16* __restrict__ wbl,
                            bf16* __restrict__ wkh, bf16* __restrict__ wkl,
                            uint2* __restrict__ ch, uint2* __restrict__ cl,
                            const float4* __restrict__ hx,
                            const float4* __restrict__ hs,
                            const float4* __restrict__ eq,
                            const unsigned char* __restrict__ dblp) {
    int bid = blockIdx.x;
    if (bid == 1280) {
        __shared__ int any;
        if (threadIdx.x == 0) any = 0;
        __syncthreads();
        int found = 0;
        for (int i = threadIdx.x; i < 2048; i += 256)
            if ((i & 3) && dblp[i]) found = 1;
        if (found) any = 1;
        __syncthreads();
        if (threadIdx.x == 0) g_dbl_is_u8 = any;
        return;
    }
    if (bid > 1280) {
        int idx = (bid - 1281) * 256 + threadIdx.x;   // BB*384 float4s
        int b = idx / 384;
        int r = idx - b * 384;
        float4 v;
        if (r < 128)       v = hx[b * 128 + r];
        else if (r < 256)  v = hs[b * 128 + (r - 128)];
        else               v = eq[b * 128 + (r - 256)];
        bf16 h0,l0,h1,l1,h2,l2,h3,l3;
        split_bf16(v.x,h0,l0); split_bf16(v.y,h1,l1);
        split_bf16(v.z,h2,l2); split_bf16(v.w,h3,l3);
        __nv_bfloat162 H01 = {h0,h1}, H23 = {h2,h3}, L01 = {l0,l1}, L23 = {l2,l3};
        ch[idx] = make_uint2(*(uint32_t*)&H01, *(uint32_t*)&H23);
        cl[idx] = make_uint2(*(uint32_t*)&L01, *(uint32_t*)&L23);
        return;
    }
    int tx = threadIdx.x & 31, ty = threadIdx.x >> 5;   // 32 x 8
    const float* in; bf16 *oh, *ol; int Cn, bx, by, roff;
    if (bid < 768)       { in = Wq; oh = wbh; ol = wbl; Cn = K3; bx = bid % 48;          by = bid / 48;         roff = 0; }
    else if (bid < 1024) { in = Wk; oh = wkh; ol = wkl; Cn = DH; bx = (bid - 768) & 15;  by = (bid - 768) >> 4; roff = 0; }
    else                 { in = Wv; oh = wbh; ol = wbl; Cn = DH; bx = (bid - 1024) & 15; by = (bid - 1024) >> 4; roff = K3; }
    __shared__ float t[32][33];
    int i0 = bx * 32, e0 = by * 32;
    #pragma unroll
    for (int j = 0; j < 32; j += 8)
        t[ty + j][tx] = in[(size_t)(e0 + ty + j) * Cn + i0 + tx];
    __syncthreads();
    #pragma unroll
    for (int j = 0; j < 32; j += 8) {
        float f = t[tx][ty + j];
        bf16 h, l; split_bf16(f, h, l);
        size_t o = (size_t)(roff + i0 + ty + j) * DH + e0 + tx;
        oh[o] = h; ol[o] = l;
    }
}

// ---------------- mma.sync GEMM: BK=64, 2-stage ----------------
// MODE 0: fp32 out, 2D grid. MODE 2: fold split-out, 2D grid.
// MODE 3: fp32 out, 1D grid (256 GEMM blocks) + 40 trailing L2-prefetch blocks.
#define MG_PITCH 144
#define MG_AH   0
#define MG_AL   9216
#define MG_BH   18432
#define MG_BL   27648
#define MG_STG  36864
#define MG_SMEM (2 * MG_STG)
#define PF_F4   114688     // float4s per prefetch block (1.75 MB); 40 blocks = 70 MB

template<int MODE>
__global__ void __launch_bounds__(128, 2) mma_gemm_kernel(
    float* __restrict__ outf,
    bf16* __restrict__ o1h, bf16* __restrict__ o1l,
    bf16* __restrict__ o2h, bf16* __restrict__ o2l,
    const bf16* __restrict__ Ah, const bf16* __restrict__ Al,
    const bf16* __restrict__ Bh, const bf16* __restrict__ Bl,
    int N, int K,
    const float4* __restrict__ pf, uint32_t* __restrict__ pf_sink)
{
    extern __shared__ char dsm[];
    uint32_t sb0 = smem_u32(dsm);

    int tid = threadIdx.x;
    int bx, by;
    if (MODE == 3) {
        int bid = blockIdx.x;
        if (bid >= 256) {
            // L2 prefetch block: stream a 1.75MB slice of HtC head into L2
            int p = bid - 256;            // 0..39
            const float4* src = pf + (size_t)p * PF_F4;
            uint32_t acc = 0;
            for (int i = tid; i < PF_F4; i += 1024) {
                #pragma unroll
                for (int j = 0; j < 8; j++)
                    acc ^= __float_as_uint(src[i + j * 128].x);
            }
            // deterministic sink write (one per warp lane 0 suffices, keep all)
            if (tid == 0) pf_sink[p] = acc;
            return;
        }
        bx = bid & 7; by = bid >> 3;
    } else {
        bx = blockIdx.x; by = blockIdx.y;
    }

    int lane = tid & 31, wid = tid >> 5;
    int wm = wid & 1, wn = wid >> 1;
    int gid = lane >> 2, tid4 = lane & 3;
    int lr = lane & 7, sel = lane >> 3;
    int bm = by * 64, bn = bx * 64;
    int KB = K >> 6;

    uint32_t a_row    = (uint32_t)(wm * 32 + lr + (sel & 1) * 8);
    uint32_t a_coloff = (uint32_t)((sel >> 1) * 8);
    uint32_t b_row    = (uint32_t)(wn * 32 + lr + (sel >> 1) * 8);
    uint32_t b_coloff = (uint32_t)((sel & 1) * 8);

    float C[2][4][4];
    #pragma unroll
    for (int t = 0; t < 2; t++)
        #pragma unroll
        for (int j = 0; j < 4; j++)
            #pragma unroll
            for (int q = 0; q < 4; q++) C[t][j][q] = 0.f;

    auto load_stage = [&](int kb, int s) {
        uint32_t sb = sb0 + s * MG_STG;
        int ko = kb * 64;
        #pragma unroll
        for (int i = 0; i < 16; i++) {
            const int tile = i >> 2;
            int u = tid + (i & 3) * 128;
            int r = u >> 3, c = u & 7;
            const bf16* src; uint32_t off; int rowb;
            if (tile == 0)      { src = Ah; off = MG_AH; rowb = bm; }
            else if (tile == 1) { src = Al; off = MG_AL; rowb = bm; }
            else if (tile == 2) { src = Bh; off = MG_BH; rowb = bn; }
            else                { src = Bl; off = MG_BL; rowb = bn; }
            cp_async16(sb + off + (uint32_t)(r * MG_PITCH + c * 16),
                       src + (size_t)(rowb + r) * K + ko + c * 8);
        }
        cp_commit();
    };

    load_stage(0, 0);

    for (int kb = 0; kb < KB; kb++) {
        if (kb + 1 < KB) {
            load_stage(kb + 1, (kb + 1) & 1);
            asm volatile("cp.async.wait_group 1;" ::: "memory");
        } else {
            asm volatile("cp.async.wait_group 0;" ::: "memory");
        }
        __syncthreads();

        uint32_t st = sb0 + (kb & 1) * MG_STG;
        #pragma unroll
        for (int step = 0; step < 4; step++) {
            int kbase = step * 16;
            uint32_t ah[2][4], al[2][4], bh[8], bl[8];
            #pragma unroll
            for (int t = 0; t < 2; t++) {
                uint32_t aa = st + MG_AH + (a_row + t * 16) * MG_PITCH + (kbase + a_coloff) * 2;
                ldmx4(ah[t], aa);
                ldmx4(al[t], aa + (MG_AL - MG_AH));
            }
            #pragma unroll
            for (int jp = 0; jp < 2; jp++) {
                uint32_t ba = st + MG_BH + (b_row + jp * 16) * MG_PITCH + (kbase + b_coloff) * 2;
                ldmx4(&bh[jp * 4], ba);
                ldmx4(&bl[jp * 4], ba + (MG_BL - MG_BH));
            }
            #pragma unroll
            for (int t = 0; t < 2; t++)
                #pragma unroll
                for (int j = 0; j < 4; j++) {
                    mma_bf16(C[t][j], ah[t], &bh[j * 2]);
                    mma_bf16(C[t][j], ah[t], &bl[j * 2]);
                    mma_bf16(C[t][j], al[t], &bh[j * 2]);
                }
        }
        __syncthreads();
    }

    bf16 *ph = o1h, *pl = o1l;
    int nstride = K3, coff = 0;
    if (MODE == 2 && bn >= K3) { ph = o2h; pl = o2l; nstride = DH; coff = K3; }
    #pragma unroll
    for (int t = 0; t < 2; t++) {
        int m0 = bm + wm * 32 + t * 16 + gid;
        #pragma unroll
        for (int j = 0; j < 4; j++) {
            int col = bn + wn * 32 + j * 8 + tid4 * 2;
            if (MODE == 2) {
                bf16 h0,l0,h1,l1;
                split_bf16(C[t][j][0], h0, l0); split_bf16(C[t][j][1], h1, l1);
                __nv_bfloat162 H = {h0,h1}, L = {l0,l1};
                *(uint32_t*)(ph + (size_t)m0 * nstride + col - coff) = *(uint32_t*)&H;
                *(uint32_t*)(pl + (size_t)m0 * nstride + col - coff) = *(uint32_t*)&L;
                split_bf16(C[t][j][2], h0, l0); split_bf16(C[t][j][3], h1, l1);
                __nv_bfloat162 H2 = {h0,h1}, L2 = {l0,l1};
                *(uint32_t*)(ph + (size_t)(m0 + 8) * nstride + col - coff) = *(uint32_t*)&H2;
                *(uint32_t*)(pl + (size_t)(m0 + 8) * nstride + col - coff) = *(uint32_t*)&L2;
            } else {
                *(float2*)(outf + (size_t)m0 * N + col)       = make_float2(C[t][j][0], C[t][j][1]);
                *(float2*)(outf + (size_t)(m0 + 8) * N + col) = make_float2(C[t][j][2], C[t][j][3]);
            }
        }
    }
}

// ---------------- fused pass 1: vectorized gbar + factored embeddings ----------------
__global__ void __launch_bounds__(512, 4) fused1_kernel(
    const float* __restrict__ HtC, const int* __restrict__ caps,
    const int* __restrict__ dists, const float* __restrict__ cemb,
    const float* __restrict__ demb, const float* __restrict__ qt,
    bf16* __restrict__ gbh, bf16* __restrict__ gbl)
{
    int b = blockIdx.x, tid = threadIdx.x;
    int w = tid >> 5, l = tid & 31;
    __shared__ __align__(16) float qs[DH];
    __shared__ __align__(16) float pr[4][DH];
    __shared__ int   cap_s[CC], dist_s[CC];
    __shared__ float cq_s[11], dq_s[3], wcap_s[11], wdist_s[3];
    __shared__ float logit_s[CC], attn_s[CC];

    qs[tid] = qt[(size_t)b * DH + tid];
    if (tid < CC) {
        cap_s[tid]  = caps[b * CC + tid];
        dist_s[tid] = dists[b * CC + tid];
    }
    __syncthreads();

    if (w < 14) {
        const float* trow = (w < 11) ? cemb + w * DH : demb + (w - 11) * DH;
        float a = 0.f;
        #pragma unroll
        for (int i = l; i < DH; i += 32) a += trow[i] * qs[i];
        #pragma unroll
        for (int o = 16; o; o >>= 1) a += __shfl_xor_sync(0xffffffffu, a, o);
        if (l == 0) { if (w < 11) cq_s[w] = a; else dq_s[w - 11] = a; }
    }

    const float4* H4 = (const float4*)HtC + (size_t)b * (CC * DH / 4);
    const float4* q4 = (const float4*)qs;
    float accr[4];
    #pragma unroll
    for (int r = 0; r < 4; r++) {
        const float4* hrow = H4 + (w * 4 + r) * 128;
        float acc = 0.f;
        #pragma unroll
        for (int j = 0; j < 4; j++) {
            int i = j * 32 + l;
            float4 h = hrow[i], q = q4[i];
            acc += h.x * q.x + h.y * q.y + h.z * q.z + h.w * q.w;
        }
        accr[r] = acc;
    }
    #pragma unroll
    for (int o = 16; o; o >>= 1) {
        accr[0] += __shfl_xor_sync(0xffffffffu, accr[0], o);
        accr[1] += __shfl_xor_sync(0xffffffffu, accr[1], o);
        accr[2] += __shfl_xor_sync(0xffffffffu, accr[2], o);
        accr[3] += __shfl_xor_sync(0xffffffffu, accr[3], o);
    }
    if (l == 0) {
        logit_s[w * 4 + 0] = accr[0];
        logit_s[w * 4 + 1] = accr[1];
        logit_s[w * 4 + 2] = accr[2];
        logit_s[w * 4 + 3] = accr[3];
    }
    __syncthreads();

    if (w == 0) {
        float x0 = (logit_s[l]      + cq_s[cap_s[l]]      + dq_s[dist_s[l]])      * SCALE;
        float x1 = (logit_s[l + 32] + cq_s[cap_s[l + 32]] + dq_s[dist_s[l + 32]]) * SCALE;
        float m = fmaxf(x0, x1);
        #pragma unroll
        for (int o = 16; o; o >>= 1) m = fmaxf(m, __shfl_xor_sync(0xffffffffu, m, o));
        float e0 = expf(x0 - m), e1 = expf(x1 - m);
        float s = e0 + e1;
        #pragma unroll
        for (int o = 16; o; o >>= 1) s += __shfl_xor_sync(0xffffffffu, s, o);
        float inv = 1.f / s;
        attn_s[l] = e0 * inv; attn_s[l + 32] = e1 * inv;
    }
    __syncthreads();

    if (tid < 11) {
        float s = 0.f;
        for (int c = 0; c < CC; c++) if (cap_s[c] == tid) s += attn_s[c];
        wcap_s[tid] = s;
    }
    if (tid >= 32 && tid < 35) {
        int u = tid - 32; float s = 0.f;
        for (int c = 0; c < CC; c++) if (dist_s[c] == u) s += attn_s[c];
        wdist_s[u] = s;
    }

    {
        int g = tid >> 7, dq = tid & 127;
        const float4* Hb4 = H4;
        float4 e0 = make_float4(0.f, 0.f, 0.f, 0.f);
        float4 e1 = make_float4(0.f, 0.f, 0.f, 0.f);
        #pragma unroll
        for (int i = 0; i < 16; i += 2) {
            int c0 = g * 16 + i;
            float4 h0 = Hb4[(c0 + 0) * 128 + dq];
            float4 h1 = Hb4[(c0 + 1) * 128 + dq];
            float a0 = attn_s[c0 + 0], a1 = attn_s[c0 + 1];
            e0.x = fmaf(a0, h0.x, e0.x); e0.y = fmaf(a0, h0.y, e0.y);
            e0.z = fmaf(a0, h0.z, e0.z); e0.w = fmaf(a0, h0.w, e0.w);
            e1.x = fmaf(a1, h1.x, e1.x); e1.y = fmaf(a1, h1.y, e1.y);
            e1.z = fmaf(a1, h1.z, e1.z); e1.w = fmaf(a1, h1.w, e1.w);
        }
        float4 tot = make_float4(e0.x + e1.x, e0.y + e1.y, e0.z + e1.z, e0.w + e1.w);
        *(float4*)&pr[g][dq * 4] = tot;
    }
    __syncthreads();

    float acc = (pr[0][tid] + pr[1][tid]) + (pr[2][tid] + pr[3][tid]);
    #pragma unroll
    for (int v = 0; v < 11; v++)
        acc = fmaf(wcap_s[v], cemb[v * DH + tid], acc);
    #pragma unroll
    for (int u = 0; u < 3; u++)
        acc = fmaf(wdist_s[u], demb[u * DH + tid], acc);
    bf16 h, lo; split_bf16(acc, h, lo);
    gbh[(size_t)b * DH + tid] = h;
    gbl[(size_t)b * DH + tid] = lo;
}

// ---------------- fused pass 2: REVERSED batch order (L2 residue from fused1) ----------------
__global__ void __launch_bounds__(512, 4) fused2_kernel(
    const float* __restrict__ HtC, const int* __restrict__ caps,
    const int* __restrict__ dists, const float* __restrict__ cemb,
    const float* __restrict__ demb, const float* __restrict__ kt,
    const void* __restrict__ dbl, float* __restrict__ out)
{
    int b = (BB - 1) - blockIdx.x;     // reversed: hit fused1's L2 tail
    int tid = threadIdx.x;
    int w = tid >> 5, l = tid & 31;
    __shared__ __align__(16) float ks[DH];
    __shared__ int   cap_s[CC], dist_s[CC];
    __shared__ float ck_s[11], dk_s[3];
    __shared__ float u_s[CC];

    ks[tid] = kt[(size_t)b * DH + tid];
    if (tid < CC) {
        cap_s[tid]  = caps[b * CC + tid];
        dist_s[tid] = dists[b * CC + tid];
    }
    __syncthreads();

    if (w < 14) {
        const float* trow = (w < 11) ? cemb + w * DH : demb + (w - 11) * DH;
        float a = 0.f;
        #pragma unroll
        for (int i = l; i < DH; i += 32) a += trow[i] * ks[i];
        #pragma unroll
        for (int o = 16; o; o >>= 1) a += __shfl_xor_sync(0xffffffffu, a, o);
        if (l == 0) { if (w < 11) ck_s[w] = a; else dk_s[w - 11] = a; }
    }

    const float4* H4 = (const float4*)HtC + (size_t)b * (CC * DH / 4);
    const float4* k4 = (const float4*)ks;
    float accr[4];
    #pragma unroll
    for (int r = 0; r < 4; r++) {
        const float4* hrow = H4 + (w * 4 + r) * 128;
        float acc = 0.f;
        #pragma unroll
        for (int j = 0; j < 4; j++) {
            int i = j * 32 + l;
            float4 h = __ldcs(hrow + i);
            float4 q = k4[i];
            acc += h.x * q.x + h.y * q.y + h.z * q.z + h.w * q.w;
        }
        accr[r] = acc;
    }
    #pragma unroll
    for (int o = 16; o; o >>= 1) {
        accr[0] += __shfl_xor_sync(0xffffffffu, accr[0], o);
        accr[1] += __shfl_xor_sync(0xffffffffu, accr[1], o);
        accr[2] += __shfl_xor_sync(0xffffffffu, accr[2], o);
        accr[3] += __shfl_xor_sync(0xffffffffu, accr[3], o);
    }
    if (l == 0) {
        u_s[w * 4 + 0] = accr[0];
        u_s[w * 4 + 1] = accr[1];
        u_s[w * 4 + 2] = accr[2];
        u_s[w * 4 + 3] = accr[3];
    }
    __syncthreads();

    if (w == 0) {
        int dval = g_dbl_is_u8 ? (int)((const unsigned char*)dbl)[b]
                               : ((const int*)dbl)[b];
        int need = dval ? 2 : 1;
        float x0 = (u_s[l]      + ck_s[cap_s[l]]      + dk_s[dist_s[l]])      * SCALE;
        float x1 = (u_s[l + 32] + ck_s[cap_s[l + 32]] + dk_s[dist_s[l + 32]]) * SCALE;
        if (cap_s[l]      < need) x0 = __int_as_float(0xff800000);
        if (cap_s[l + 32] < need) x1 = __int_as_float(0xff800000);
        float m = fmaxf(x0, x1);
        #pragma unroll
        for (int o = 16; o; o >>= 1) m = fmaxf(m, __shfl_xor_sync(0xffffffffu, m, o));
        float e0 = expf(x0 - m), e1 = expf(x1 - m);
        float s = e0 + e1;
        #pragma unroll
        for (int o = 16; o; o >>= 1) s += __shfl_xor_sync(0xffffffffu, s, o);
        float inv = 1.f / s;
        out[(size_t)b * CC + l]      = e0 * inv;
        out[(size_t)b * CC + l + 32] = e1 * inv;
    }
}

extern "C" void kernel_launch(void* const* d_in, const int* in_sizes, int n_in,
                              void* d_out, int out_size) {
    const float* HtC   = (const float*)d_in[0];
    const int*   caps  = (const int*)  d_in[1];
    const int*   dists = (const int*)  d_in[2];
    const float* HX    = (const float*)d_in[3];
    const float* HS    = (const float*)d_in[4];
    const float* EQ    = (const float*)d_in[5];
    const void*  dbl   = d_in[6];
    const float* cemb  = (const float*)d_in[7];
    const float* demb  = (const float*)d_in[8];
    const float* Wq    = (const float*)d_in[9];
    const float* Wk    = (const float*)d_in[10];
    const float* Wv    = (const float*)d_in[11];
    float* out = (float*)d_out;

    bf16 *ctxh,*ctxl,*wbh,*wbl,*wkh,*wkl,*w1h,*w1l,*m2h,*m2l,*gbh,*gbl;
    float *qt,*kt;
    uint32_t *pfs;
    cudaGetSymbolAddress((void**)&ctxh, g_ctx_h);  cudaGetSymbolAddress((void**)&ctxl, g_ctx_l);
    cudaGetSymbolAddress((void**)&wbh,  g_WBT_h);  cudaGetSymbolAddress((void**)&wbl,  g_WBT_l);
    cudaGetSymbolAddress((void**)&wkh,  g_WkT_h);  cudaGetSymbolAddress((void**)&wkl,  g_WkT_l);
    cudaGetSymbolAddress((void**)&w1h,  g_W1t_h);  cudaGetSymbolAddress((void**)&w1l,  g_W1t_l);
    cudaGetSymbolAddress((void**)&m2h,  g_M2t_h);  cudaGetSymbolAddress((void**)&m2l,  g_M2t_l);
    cudaGetSymbolAddress((void**)&gbh,  g_gbar_h); cudaGetSymbolAddress((void**)&gbl,  g_gbar_l);
    cudaGetSymbolAddress((void**)&qt,   g_qt);     cudaGetSymbolAddress((void**)&kt,   g_kt);
    cudaGetSymbolAddress((void**)&pfs,  g_pf_sink);

    cudaFuncSetAttribute(mma_gemm_kernel<0>, cudaFuncAttributeMaxDynamicSharedMemorySize, MG_SMEM);
    cudaFuncSetAttribute(mma_gemm_kernel<2>, cudaFuncAttributeMaxDynamicSharedMemorySize, MG_SMEM);
    cudaFuncSetAttribute(mma_gemm_kernel<3>, cudaFuncAttributeMaxDynamicSharedMemorySize, MG_SMEM);

    // 1) prep: weight transposes (B concat) + context pack/split + dtype sniff
    prep_kernel<<<4353, 256>>>(Wq, Wk, Wv, wbh, wbl, wkh, wkl,
                               (uint2*)ctxh, (uint2*)ctxl,
                               (const float4*)HX, (const float4*)HS, (const float4*)EQ,
                               (const unsigned char*)dbl);
    // 2) fold (merged): W1t | M2t
    mma_gemm_kernel<2><<<dim3(NB2/64, DH/64), 128, MG_SMEM>>>(
        nullptr, w1h, w1l, m2h, m2l, wkh, wkl, wbh, wbl, NB2, DH, nullptr, nullptr);
    // 3) qt GEMM (1D grid, 256 GEMM + 40 HtC-prefetch blocks)
    mma_gemm_kernel<3><<<296, 128, MG_SMEM>>>(
        qt, nullptr, nullptr, nullptr, nullptr, ctxh, ctxl, w1h, w1l, DH, K3,
        (const float4*)HtC, pfs);
    // 4) logits/softmax/gbar
    fused1_kernel<<<BB, 512>>>(HtC, caps, dists, cemb, demb, qt, gbh, gbl);
    // 5) kt GEMM
    mma_gemm_kernel<0><<<dim3(DH/64, BB/64), 128, MG_SMEM>>>(
        kt, nullptr, nullptr, nullptr, nullptr, gbh, gbl, m2h, m2l, DH, DH,
        nullptr, nullptr);
    // 6) u/mask/softmax -> out (reversed batch order)
    fused2_kernel<<<BB, 512>>>(HtC, caps, dists, cemb, demb, kt, dbl, out);
}